// round 1
// baseline (speedup 1.0000x reference)
#include <cuda_runtime.h>
#include <cstdint>

// Problem constants
#define NB   4096   // batch B
#define NM   8192   // memory rows M
#define ND   1024   // dim D
#define NOUT 1000   // output classes
#define NH   4096   // 4*D hidden
#define N2D  2048   // 2*D concat width

// -------- scratch (device globals; no allocation allowed) --------
__device__ float g_xnorm[(size_t)NB * ND];    // 16 MB  normalized encoder
__device__ float g_yinv[NM];                  // 32 KB  1/||mem_row||
__device__ float g_sim[(size_t)NB * NM];      // 128 MB cosine sims
__device__ float g_concat[(size_t)NB * N2D];  // 32 MB  [enc | memory_vector]
__device__ float g_hidden[(size_t)NB * NH];   // 64 MB  relu(fc1)

// ---------------------------------------------------------------
// block reduce (256 threads)
// ---------------------------------------------------------------
__device__ __forceinline__ float blockReduceSum256(float v, float* red) {
    __syncthreads();  // protect red[] from previous use
    #pragma unroll
    for (int o = 16; o > 0; o >>= 1) v += __shfl_down_sync(0xffffffffu, v, o);
    int warp = threadIdx.x >> 5, lane = threadIdx.x & 31;
    if (lane == 0) red[warp] = v;
    __syncthreads();
    if (warp == 0) {
        v = (lane < 8) ? red[lane] : 0.0f;
        #pragma unroll
        for (int o = 4; o > 0; o >>= 1) v += __shfl_down_sync(0xffffffffu, v, o);
        if (lane == 0) red[0] = v;
    }
    __syncthreads();
    return red[0];
}

// ---------------------------------------------------------------
// normalize encoder rows: write x_norm, and copy raw enc into concat[:, :D]
// grid = NB blocks, 256 threads (1024 floats = 256 float4 per row)
// ---------------------------------------------------------------
__global__ __launch_bounds__(256) void norm_enc_kernel(const float* __restrict__ enc) {
    __shared__ float red[8];
    int row = blockIdx.x, tid = threadIdx.x;
    float4 v = ((const float4*)(enc + (size_t)row * ND))[tid];
    float s = v.x*v.x + v.y*v.y + v.z*v.z + v.w*v.w;
    s = blockReduceSum256(s, red);
    float inv = rsqrtf(s + 1e-6f);
    float4 o = make_float4(v.x*inv, v.y*inv, v.z*inv, v.w*inv);
    ((float4*)(g_xnorm  + (size_t)row * ND ))[tid] = o;
    ((float4*)(g_concat + (size_t)row * N2D))[tid] = v;   // raw enc, left half
}

// ---------------------------------------------------------------
// memory row inverse norms: g_yinv[m] = 1/sqrt(sum(mem[m]^2)+eps)
// grid = NM blocks, 256 threads
// ---------------------------------------------------------------
__global__ __launch_bounds__(256) void norm_mem_kernel(const float* __restrict__ mem) {
    __shared__ float red[8];
    int row = blockIdx.x, tid = threadIdx.x;
    float4 v = ((const float4*)(mem + (size_t)row * ND))[tid];
    float s = v.x*v.x + v.y*v.y + v.z*v.z + v.w*v.w;
    s = blockReduceSum256(s, red);
    if (tid == 0) g_yinv[row] = rsqrtf(s + 1e-6f);
}

// ---------------------------------------------------------------
// SGEMM  C[M,N] = A[M,K] * B[N,K]^T   (both row-major, "TN")
// optional per-column scale, bias, relu epilogue.
// 128x128 block, BK=16, 256 threads, 8x8 per-thread (split 4+4 tiles).
// M must be a multiple of 128 and K a multiple of 16 (true for all calls);
// N is bounds-guarded.
// ---------------------------------------------------------------
template<bool SCALE, bool BIAS, bool RELU>
__global__ __launch_bounds__(256) void sgemm_tn_kernel(
    int M, int N, int K,
    const float* __restrict__ A, const float* __restrict__ B,
    float* __restrict__ C,
    const float* __restrict__ scale, const float* __restrict__ bias)
{
    constexpr int BM = 128, BN = 128, BK = 16;
    __shared__ float As[BK][BM];
    __shared__ float Bs[BK][BN];

    const int tid = threadIdx.x;
    const int tx = tid & 15;   // 0..15 along N
    const int ty = tid >> 4;   // 0..15 along M
    const int row0 = blockIdx.y * BM;
    const int col0 = blockIdx.x * BN;

    float acc[8][8];
    #pragma unroll
    for (int i = 0; i < 8; i++)
        #pragma unroll
        for (int j = 0; j < 8; j++) acc[i][j] = 0.0f;

    const int nk = K / BK;
    for (int kt = 0; kt < nk; ++kt) {
        // load A tile (128x16): 512 float4, 2 per thread
        #pragma unroll
        for (int l = 0; l < 2; ++l) {
            int lin = tid + l * 256;
            int r  = lin >> 2;            // 0..127
            int kq = (lin & 3) << 2;      // 0,4,8,12
            float4 v = *(const float4*)(A + (size_t)(row0 + r) * K + (kt * BK + kq));
            As[kq + 0][r] = v.x; As[kq + 1][r] = v.y;
            As[kq + 2][r] = v.z; As[kq + 3][r] = v.w;
        }
        // load B tile (128x16) with N bounds
        #pragma unroll
        for (int l = 0; l < 2; ++l) {
            int lin = tid + l * 256;
            int r  = lin >> 2;
            int kq = (lin & 3) << 2;
            int c  = col0 + r;
            float4 v = make_float4(0.f, 0.f, 0.f, 0.f);
            if (c < N) v = *(const float4*)(B + (size_t)c * K + (kt * BK + kq));
            Bs[kq + 0][r] = v.x; Bs[kq + 1][r] = v.y;
            Bs[kq + 2][r] = v.z; Bs[kq + 3][r] = v.w;
        }
        __syncthreads();

        #pragma unroll
        for (int kk = 0; kk < BK; ++kk) {
            float a[8], b[8];
            *(float4*)&a[0] = *(const float4*)&As[kk][ty * 4];
            *(float4*)&a[4] = *(const float4*)&As[kk][64 + ty * 4];
            *(float4*)&b[0] = *(const float4*)&Bs[kk][tx * 4];
            *(float4*)&b[4] = *(const float4*)&Bs[kk][64 + tx * 4];
            #pragma unroll
            for (int i = 0; i < 8; i++)
                #pragma unroll
                for (int j = 0; j < 8; j++)
                    acc[i][j] += a[i] * b[j];
        }
        __syncthreads();
    }

    // epilogue
    #pragma unroll
    for (int i = 0; i < 8; i++) {
        int row = row0 + ((i < 4) ? (ty * 4 + i) : (64 + ty * 4 + (i - 4)));
        #pragma unroll
        for (int j = 0; j < 8; j++) {
            int col = col0 + ((j < 4) ? (tx * 4 + j) : (64 + tx * 4 + (j - 4)));
            if (col < N) {
                float v = acc[i][j];
                if (SCALE) v *= scale[col];
                if (BIAS)  v += bias[col];
                if (RELU)  v = fmaxf(v, 0.0f);
                C[(size_t)row * N + col] = v;
            }
        }
    }
}

// ---------------------------------------------------------------
// Fused sparsemax (Michelot, sort-free) + sparse memory-vector gather.
// One CTA per batch row. sparsemax(sim_row) -> weights (support ~tens),
// then mv[d] = sum_{supp} w * mem[idx, d], written into concat[:, D:2D].
// Deterministic compaction (prefix scan, no atomics).
// ---------------------------------------------------------------
#define SPX_CAP 4096
__global__ __launch_bounds__(256) void sparsemax_mv_kernel(const float* __restrict__ mem) {
    __shared__ float z[NM];                 // 32 KB
    __shared__ unsigned short idxs[SPX_CAP];// 8 KB
    __shared__ float redS[8];
    __shared__ float redC[8];
    __shared__ int   counts[257];
    __shared__ float tau_sh;
    __shared__ int   cprev_sh;
    __shared__ int   done_sh;

    const int row = blockIdx.x;
    const int tid = threadIdx.x;

    // load sim row into smem (8192 floats = 2048 float4)
    const float4* src = (const float4*)(g_sim + (size_t)row * NM);
    #pragma unroll
    for (int l = 0; l < 8; ++l)
        ((float4*)z)[tid + l * 256] = src[tid + l * 256];
    __syncthreads();

    // initial tau from full support
    {
        float s = 0.0f;
        #pragma unroll
        for (int l = 0; l < 32; ++l) s += z[tid + l * 256];
        s = blockReduceSum256(s, redS);
        if (tid == 0) {
            tau_sh = (s - 1.0f) / (float)NM;
            cprev_sh = NM;
            done_sh = 0;
        }
        __syncthreads();
    }

    // Michelot iterations: tau <- (sum_{z>tau} z - 1) / count
    for (int it = 0; it < 64; ++it) {
        float tau = tau_sh;
        float ls = 0.0f, lc = 0.0f;
        #pragma unroll
        for (int l = 0; l < 32; ++l) {
            float v = z[tid + l * 256];
            if (v > tau) { ls += v; lc += 1.0f; }
        }
        // reduce (sum, count)
        #pragma unroll
        for (int o = 16; o > 0; o >>= 1) {
            ls += __shfl_down_sync(0xffffffffu, ls, o);
            lc += __shfl_down_sync(0xffffffffu, lc, o);
        }
        int warp = tid >> 5, lane = tid & 31;
        if (lane == 0) { redS[warp] = ls; redC[warp] = lc; }
        __syncthreads();
        if (tid == 0) {
            float S = 0.0f, Cc = 0.0f;
            #pragma unroll
            for (int w = 0; w < 8; ++w) { S += redS[w]; Cc += redC[w]; }
            int c = (int)(Cc + 0.5f);
            if (c == cprev_sh || c <= 0) {
                done_sh = 1;
            } else {
                cprev_sh = c;
                tau_sh = (S - 1.0f) / (float)c;
            }
        }
        __syncthreads();
        if (done_sh) break;
    }
    const float tau = tau_sh;

    // deterministic compaction: each thread owns z[tid*32 .. tid*32+31]
    int mycnt = 0;
    {
        int base = tid * 32;
        #pragma unroll
        for (int i = 0; i < 32; ++i)
            if (z[base + i] > tau) mycnt++;
    }
    counts[tid] = mycnt;
    __syncthreads();
    if (tid == 0) {
        int run = 0;
        for (int t = 0; t < 256; ++t) { int c = counts[t]; counts[t] = run; run += c; }
        counts[256] = run;
    }
    __syncthreads();
    const int nnz = counts[256];
    if (nnz <= SPX_CAP) {
        int off = counts[tid];
        int base = tid * 32;
        #pragma unroll
        for (int i = 0; i < 32; ++i)
            if (z[base + i] > tau) idxs[off++] = (unsigned short)(base + i);
    }
    __syncthreads();

    // sparse MV: each thread accumulates cols [4*tid, 4*tid+4)
    float4 acc = make_float4(0.f, 0.f, 0.f, 0.f);
    const float4* mem4 = (const float4*)mem;
    if (nnz <= SPX_CAP) {
        #pragma unroll 4
        for (int j = 0; j < nnz; ++j) {
            int m = idxs[j];
            float w = z[m] - tau;
            float4 v = mem4[(size_t)m * 256 + tid];
            acc.x += w * v.x; acc.y += w * v.y;
            acc.z += w * v.z; acc.w += w * v.w;
        }
    } else {
        // pathological fallback: dense, still deterministic
        for (int m = 0; m < NM; ++m) {
            float w = z[m] - tau;
            if (w > 0.0f) {
                float4 v = mem4[(size_t)m * 256 + tid];
                acc.x += w * v.x; acc.y += w * v.y;
                acc.z += w * v.z; acc.w += w * v.w;
            }
        }
    }
    ((float4*)(g_concat + (size_t)row * N2D + ND))[tid] = acc;
}

// ---------------------------------------------------------------
// launch
// ---------------------------------------------------------------
extern "C" void kernel_launch(void* const* d_in, const int* in_sizes, int n_in,
                              void* d_out, int out_size) {
    const float* enc   = (const float*)d_in[0];  // [4096,1024]
    const float* mem   = (const float*)d_in[1];  // [8192,1024]
    const float* fc1w  = (const float*)d_in[2];  // [4096,2048]
    const float* fc1b  = (const float*)d_in[3];  // [4096]
    const float* fc2w  = (const float*)d_in[4];  // [1000,4096]
    const float* fc2b  = (const float*)d_in[5];  // [1000]
    float* out = (float*)d_out;                  // [4096,1000]

    void *p_xnorm, *p_yinv, *p_sim, *p_concat, *p_hidden;
    cudaGetSymbolAddress(&p_xnorm,  g_xnorm);
    cudaGetSymbolAddress(&p_yinv,   g_yinv);
    cudaGetSymbolAddress(&p_sim,    g_sim);
    cudaGetSymbolAddress(&p_concat, g_concat);
    cudaGetSymbolAddress(&p_hidden, g_hidden);

    // 1) normalize encoder + stash raw enc into concat left half
    norm_enc_kernel<<<NB, 256>>>(enc);
    // 2) memory row inverse norms
    norm_mem_kernel<<<NM, 256>>>(mem);
    // 3) sim = x_norm @ mem^T, scaled per-column by 1/||mem_m||
    {
        dim3 grid(NM / 128, NB / 128);
        sgemm_tn_kernel<true, false, false><<<grid, 256>>>(
            NB, NM, ND, (const float*)p_xnorm, mem, (float*)p_sim,
            (const float*)p_yinv, nullptr);
    }
    // 4) sparsemax + sparse memory-vector into concat right half
    sparsemax_mv_kernel<<<NB, 256>>>(mem);
    // 5) hidden = relu(concat @ fc1w^T + fc1b)
    {
        dim3 grid(NH / 128, NB / 128);
        sgemm_tn_kernel<false, true, true><<<grid, 256>>>(
            NB, NH, N2D, (const float*)p_concat, fc1w, (float*)p_hidden,
            nullptr, fc1b);
    }
    // 6) out = hidden @ fc2w^T + fc2b   (N=1000, bounds-guarded)
    {
        dim3 grid((NOUT + 127) / 128, NB / 128);
        sgemm_tn_kernel<false, true, false><<<grid, 256>>>(
            NB, NOUT, NH, (const float*)p_hidden, fc2w, out,
            nullptr, fc2b);
    }
}

// round 3
// speedup vs baseline: 1.3961x; 1.3961x over previous
#include <cuda_runtime.h>
#include <cuda_bf16.h>
#include <cstdint>

// Problem constants
#define NB   4096   // batch B
#define NM   8192   // memory rows M
#define ND   1024   // dim D
#define NOUT 1000   // output classes
#define NOUTP 1024  // padded output cols
#define NH   4096   // 4*D hidden
#define N2D  2048   // 2*D concat width

typedef __nv_bfloat16 bf16;

// -------- scratch (device globals; no allocation allowed) --------
__device__ float g_xinv[NB];
__device__ float g_yinv[NM];
__device__ float g_sim[(size_t)NB * NM];        // 128 MB
__device__ bf16  g_cat_hi[(size_t)NB * N2D];    // 16 MB  [enc_hi | mv_hi]
__device__ bf16  g_cat_lo[(size_t)NB * N2D];    // 16 MB
__device__ bf16  g_mem_hi[(size_t)NM * ND];     // 16 MB
__device__ bf16  g_mem_lo[(size_t)NM * ND];     // 16 MB
__device__ bf16  g_hid_hi[(size_t)NB * NH];     // 32 MB
__device__ bf16  g_hid_lo[(size_t)NB * NH];     // 32 MB
__device__ bf16  g_w1_hi[(size_t)NH * N2D];     // 16 MB
__device__ bf16  g_w1_lo[(size_t)NH * N2D];     // 16 MB
__device__ bf16  g_w2_hi[(size_t)NOUTP * NH];   // 8 MB (padded)
__device__ bf16  g_w2_lo[(size_t)NOUTP * NH];   // 8 MB

// ---------------------------------------------------------------
// helpers
// ---------------------------------------------------------------
__device__ __forceinline__ uint32_t cvta_smem(const void* p) {
    uint32_t a;
    asm("{ .reg .u64 t; cvta.to.shared.u64 t, %1; cvt.u32.u64 %0, t; }"
        : "=r"(a) : "l"(p));
    return a;
}

__device__ __forceinline__ void cp16(uint32_t dst, const void* src) {
    asm volatile("cp.async.cg.shared.global [%0], [%1], 16;" :: "r"(dst), "l"(src));
}

__device__ __forceinline__ void mma_bf16(float* d, const uint32_t* a, const uint32_t* b) {
    asm volatile(
        "mma.sync.aligned.m16n8k16.row.col.f32.bf16.bf16.f32 "
        "{%0,%1,%2,%3}, {%4,%5,%6,%7}, {%8,%9}, {%0,%1,%2,%3};"
        : "+f"(d[0]), "+f"(d[1]), "+f"(d[2]), "+f"(d[3])
        : "r"(a[0]), "r"(a[1]), "r"(a[2]), "r"(a[3]), "r"(b[0]), "r"(b[1]));
}

__device__ __forceinline__ void bf16_split(float v, bf16& h, bf16& l) {
    h = __float2bfloat16_rn(v);
    l = __float2bfloat16_rn(v - __bfloat162float(h));
}

// ---------------------------------------------------------------
// block reduce (256 threads)
// ---------------------------------------------------------------
__device__ __forceinline__ float blockReduceSum256(float v, float* red) {
    __syncthreads();
    #pragma unroll
    for (int o = 16; o > 0; o >>= 1) v += __shfl_down_sync(0xffffffffu, v, o);
    int warp = threadIdx.x >> 5, lane = threadIdx.x & 31;
    if (lane == 0) red[warp] = v;
    __syncthreads();
    if (warp == 0) {
        v = (lane < 8) ? red[lane] : 0.0f;
        #pragma unroll
        for (int o = 4; o > 0; o >>= 1) v += __shfl_down_sync(0xffffffffu, v, o);
        if (lane == 0) red[0] = v;
    }
    __syncthreads();
    return red[0];
}

// ---------------------------------------------------------------
// encoder: 1/||x||, and bf16 split of raw enc -> concat left half
// ---------------------------------------------------------------
__global__ __launch_bounds__(256) void norm_enc_kernel(const float* __restrict__ enc) {
    __shared__ float red[8];
    int row = blockIdx.x, tid = threadIdx.x;
    float4 v = ((const float4*)(enc + (size_t)row * ND))[tid];
    float s = v.x*v.x + v.y*v.y + v.z*v.z + v.w*v.w;
    s = blockReduceSum256(s, red);
    if (tid == 0) g_xinv[row] = rsqrtf(s + 1e-6f);
    bf16 hx, lx, hy, ly, hz, lz, hw, lw;
    bf16_split(v.x, hx, lx); bf16_split(v.y, hy, ly);
    bf16_split(v.z, hz, lz); bf16_split(v.w, hw, lw);
    bf16* ph = g_cat_hi + (size_t)row * N2D + tid * 4;
    bf16* pl = g_cat_lo + (size_t)row * N2D + tid * 4;
    ph[0] = hx; ph[1] = hy; ph[2] = hz; ph[3] = hw;
    pl[0] = lx; pl[1] = ly; pl[2] = lz; pl[3] = lw;
}

// ---------------------------------------------------------------
// memory rows: 1/||y|| + bf16 split
// ---------------------------------------------------------------
__global__ __launch_bounds__(256) void norm_mem_kernel(const float* __restrict__ mem) {
    __shared__ float red[8];
    int row = blockIdx.x, tid = threadIdx.x;
    float4 v = ((const float4*)(mem + (size_t)row * ND))[tid];
    float s = v.x*v.x + v.y*v.y + v.z*v.z + v.w*v.w;
    s = blockReduceSum256(s, red);
    if (tid == 0) g_yinv[row] = rsqrtf(s + 1e-6f);
    bf16 hx, lx, hy, ly, hz, lz, hw, lw;
    bf16_split(v.x, hx, lx); bf16_split(v.y, hy, ly);
    bf16_split(v.z, hz, lz); bf16_split(v.w, hw, lw);
    bf16* ph = g_mem_hi + (size_t)row * ND + tid * 4;
    bf16* pl = g_mem_lo + (size_t)row * ND + tid * 4;
    ph[0] = hx; ph[1] = hy; ph[2] = hz; ph[3] = hw;
    pl[0] = lx; pl[1] = ly; pl[2] = lz; pl[3] = lw;
}

// ---------------------------------------------------------------
// generic bf16 split of a contiguous fp32 array (4 elems/thread)
// ---------------------------------------------------------------
__global__ __launch_bounds__(256) void split_kernel(
    const float* __restrict__ src, bf16* __restrict__ hi, bf16* __restrict__ lo) {
    size_t i = (size_t)blockIdx.x * 256 + threadIdx.x;
    float4 v = ((const float4*)src)[i];
    bf16 hx, lx, hy, ly, hz, lz, hw, lw;
    bf16_split(v.x, hx, lx); bf16_split(v.y, hy, ly);
    bf16_split(v.z, hz, lz); bf16_split(v.w, hw, lw);
    bf16* ph = hi + i * 4;
    bf16* pl = lo + i * 4;
    ph[0] = hx; ph[1] = hy; ph[2] = hz; ph[3] = hw;
    pl[0] = lx; pl[1] = ly; pl[2] = lz; pl[3] = lw;
}

// fc2 weights: split + zero-pad rows [1000,1024)
__global__ __launch_bounds__(256) void split_pad_w2_kernel(const float* __restrict__ src) {
    int row = blockIdx.x, tid = threadIdx.x;  // 1024 rows x 4096 cols
    #pragma unroll
    for (int lq = 0; lq < 4; ++lq) {
        int idx = tid + 256 * lq;             // float4 index in row
        float4 v = make_float4(0.f, 0.f, 0.f, 0.f);
        if (row < NOUT) v = ((const float4*)(src + (size_t)row * NH))[idx];
        bf16 hx, lx, hy, ly, hz, lz, hw, lw;
        bf16_split(v.x, hx, lx); bf16_split(v.y, hy, ly);
        bf16_split(v.z, hz, lz); bf16_split(v.w, hw, lw);
        bf16* ph = g_w2_hi + (size_t)row * NH + idx * 4;
        bf16* pl = g_w2_lo + (size_t)row * NH + idx * 4;
        ph[0] = hx; ph[1] = hy; ph[2] = hz; ph[3] = hw;
        pl[0] = lx; pl[1] = ly; pl[2] = lz; pl[3] = lw;
    }
}

// ---------------------------------------------------------------
// bf16 3-pass split GEMM (mma.sync.m16n8k16):
//   C[M,N] = A[M,K] @ B[N,K]^T  with A=Ah+Al, B=Bh+Bl,
//   C ~= Ah*Bh + Al*Bh + Ah*Bl  (all accumulated in fp32 regs)
// 128x128 CTA tile, BK=64, 3-stage cp.async pipeline, 256 threads (8 warps 2x4).
// EPI: 0 = sim   (v * xinv[row] * yinv[col], fp32 store)
//      1 = fc1   (relu(v+bias) -> bf16 split stores)
//      2 = fc2   (v+bias, fp32 store guarded col<Nout, row stride Nout)
// ---------------------------------------------------------------
#define BKE     64                       // K elems per chunk
#define ROW_B   144                      // smem row stride bytes (64*2 + 16 pad)
#define AT_B    (128 * ROW_B)            // 18432 bytes per operand tile
#define STAGE_B (2 * AT_B)               // 36864
#define NSTAGE  3
#define GEMM_SMEM (NSTAGE * STAGE_B)     // 110592

template<int EPI>
__global__ __launch_bounds__(256) void tc_gemm(
    int N, int K, int lda, int ldb, int Nout,
    const bf16* __restrict__ A0, const bf16* __restrict__ A1,
    const bf16* __restrict__ B0, const bf16* __restrict__ B1,
    float* __restrict__ C, bf16* __restrict__ Ch, bf16* __restrict__ Cl,
    const float* __restrict__ xinv, const float* __restrict__ yinv,
    const float* __restrict__ bias)
{
    extern __shared__ __align__(1024) char smraw[];
    const uint32_t smemU = cvta_smem(smraw);

    const int tid  = threadIdx.x;
    const int lane = tid & 31;
    const int wid  = tid >> 5;
    const int wm   = wid & 1;          // 0..1  (64-row block)
    const int wn   = wid >> 1;         // 0..3  (32-col block)
    const int row0 = blockIdx.y * 128;
    const int col0 = blockIdx.x * 128;

    const int nkc = K / BKE;
    const int IT  = 3 * nkc;

    // load mapping: thread handles row = tid>>1, 4 x 16B chunks at (tid&1)*64B
    const int ldr = tid >> 1;          // 0..127
    const int ldc = (tid & 1) * 32;    // bf16 element offset within row (0 or 32)
    const uint32_t sdA = smemU + ldr * ROW_B + (tid & 1) * 64;
    const uint32_t sdB = sdA + AT_B;

    auto do_load = [&](int it, int s) {
        const int ck   = it % nkc;
        const int pass = it / nkc;
        const bf16* Ap = (pass == 1) ? A1 : A0;
        const bf16* Bp = (pass == 2) ? B1 : B0;
        const bf16* ga = Ap + (size_t)(row0 + ldr) * lda + ck * BKE + ldc;
        const bf16* gb = Bp + (size_t)(col0 + ldr) * ldb + ck * BKE + ldc;
        const uint32_t so = s * STAGE_B;
        #pragma unroll
        for (int i = 0; i < 4; ++i) {
            cp16(sdA + so + i * 16, ga + i * 8);
            cp16(sdB + so + i * 16, gb + i * 8);
        }
    };

    float acc[4][4][4];
    #pragma unroll
    for (int mt = 0; mt < 4; ++mt)
        #pragma unroll
        for (int nt = 0; nt < 4; ++nt)
            #pragma unroll
            for (int c = 0; c < 4; ++c) acc[mt][nt][c] = 0.0f;

    // prologue: stages 0,1
    do_load(0, 0);
    asm volatile("cp.async.commit_group;" ::: "memory");
    do_load(1, 1);
    asm volatile("cp.async.commit_group;" ::: "memory");

    const int r = lane >> 2;       // 0..7
    const int q = lane & 3;        // 0..3
    // per-warp smem byte bases for fragments
    const char* sm = smraw;

    for (int it = 0; it < IT; ++it) {
        if (it + 2 < IT) {
            asm volatile("cp.async.wait_group 1;" ::: "memory");
        } else {
            asm volatile("cp.async.wait_group 0;" ::: "memory");
        }
        __syncthreads();
        if (it + 2 < IT) {
            do_load(it + 2, (it + 2) % NSTAGE);
            asm volatile("cp.async.commit_group;" ::: "memory");
        }

        const char* As = sm + (it % NSTAGE) * STAGE_B;
        const char* Bs = As + AT_B;
        const char* aBase = As + (wm * 64 + r) * ROW_B + q * 4;
        const char* bBase = Bs + (wn * 32 + r) * ROW_B + q * 4;

        #pragma unroll
        for (int ks = 0; ks < 4; ++ks) {
            const int ko = ks * 32;    // bytes: 16 elems * 2B
            uint32_t afr[4][4], bfr[4][2];
            #pragma unroll
            for (int mt = 0; mt < 4; ++mt) {
                const char* p = aBase + mt * (16 * ROW_B) + ko;
                afr[mt][0] = *(const uint32_t*)(p);
                afr[mt][1] = *(const uint32_t*)(p + 8 * ROW_B);
                afr[mt][2] = *(const uint32_t*)(p + 16);
                afr[mt][3] = *(const uint32_t*)(p + 8 * ROW_B + 16);
            }
            #pragma unroll
            for (int nt = 0; nt < 4; ++nt) {
                const char* p = bBase + nt * (8 * ROW_B) + ko;
                bfr[nt][0] = *(const uint32_t*)(p);
                bfr[nt][1] = *(const uint32_t*)(p + 16);
            }
            #pragma unroll
            for (int mt = 0; mt < 4; ++mt)
                #pragma unroll
                for (int nt = 0; nt < 4; ++nt)
                    mma_bf16(acc[mt][nt], afr[mt], bfr[nt]);
        }
        __syncthreads();
    }

    // epilogue
    #pragma unroll
    for (int mt = 0; mt < 4; ++mt) {
        const int gr0 = row0 + wm * 64 + mt * 16 + r;
        #pragma unroll
        for (int half = 0; half < 2; ++half) {
            const int gr = gr0 + half * 8;
            float xr = 0.0f;
            if (EPI == 0) xr = xinv[gr];
            #pragma unroll
            for (int nt = 0; nt < 4; ++nt) {
                const int gc = col0 + wn * 32 + nt * 8 + q * 2;
                float v0 = acc[mt][nt][half * 2 + 0];
                float v1 = acc[mt][nt][half * 2 + 1];
                if (EPI == 0) {
                    float2 o = make_float2(v0 * xr * yinv[gc], v1 * xr * yinv[gc + 1]);
                    *(float2*)(C + (size_t)gr * N + gc) = o;
                } else if (EPI == 1) {
                    v0 = fmaxf(v0 + bias[gc], 0.0f);
                    v1 = fmaxf(v1 + bias[gc + 1], 0.0f);
                    bf16 h0, l0, h1, l1;
                    bf16_split(v0, h0, l0);
                    bf16_split(v1, h1, l1);
                    __nv_bfloat162 hh; hh.x = h0; hh.y = h1;
                    __nv_bfloat162 ll; ll.x = l0; ll.y = l1;
                    *(__nv_bfloat162*)(Ch + (size_t)gr * N + gc) = hh;
                    *(__nv_bfloat162*)(Cl + (size_t)gr * N + gc) = ll;
                } else {
                    if (gc < Nout) {
                        float2 o = make_float2(v0 + bias[gc], v1 + bias[gc + 1]);
                        *(float2*)(C + (size_t)gr * Nout + gc) = o;
                    }
                }
            }
        }
    }
}

// ---------------------------------------------------------------
// Fused sparsemax (Michelot, sort-free) + sparse memory-vector gather.
// Writes bf16 split memory vector into concat right half.
// ---------------------------------------------------------------
#define SPX_CAP 4096
__global__ __launch_bounds__(256) void sparsemax_mv_kernel(const float* __restrict__ mem) {
    __shared__ float z[NM];                  // 32 KB
    __shared__ unsigned short idxs[SPX_CAP]; // 8 KB
    __shared__ float redS[8];
    __shared__ float redC[8];
    __shared__ int   counts[257];
    __shared__ float tau_sh;
    __shared__ int   cprev_sh;
    __shared__ int   done_sh;

    const int row = blockIdx.x;
    const int tid = threadIdx.x;

    const float4* src = (const float4*)(g_sim + (size_t)row * NM);
    #pragma unroll
    for (int l = 0; l < 8; ++l)
        ((float4*)z)[tid + l * 256] = src[tid + l * 256];
    __syncthreads();

    {
        float s = 0.0f;
        #pragma unroll
        for (int l = 0; l < 32; ++l) s += z[tid + l * 256];
        s = blockReduceSum256(s, redS);
        if (tid == 0) {
            tau_sh = (s - 1.0f) / (float)NM;
            cprev_sh = NM;
            done_sh = 0;
        }
        __syncthreads();
    }

    for (int it = 0; it < 64; ++it) {
        float tau = tau_sh;
        float ls = 0.0f, lc = 0.0f;
        #pragma unroll
        for (int l = 0; l < 32; ++l) {
            float v = z[tid + l * 256];
            if (v > tau) { ls += v; lc += 1.0f; }
        }
        #pragma unroll
        for (int o = 16; o > 0; o >>= 1) {
            ls += __shfl_down_sync(0xffffffffu, ls, o);
            lc += __shfl_down_sync(0xffffffffu, lc, o);
        }
        int warp = tid >> 5, lane = tid & 31;
        if (lane == 0) { redS[warp] = ls; redC[warp] = lc; }
        __syncthreads();
        if (tid == 0) {
            float S = 0.0f, Cc = 0.0f;
            #pragma unroll
            for (int w = 0; w < 8; ++w) { S += redS[w]; Cc += redC[w]; }
            int c = (int)(Cc + 0.5f);
            if (c == cprev_sh || c <= 0) done_sh = 1;
            else { cprev_sh = c; tau_sh = (S - 1.0f) / (float)c; }
        }
        __syncthreads();
        if (done_sh) break;
    }
    const float tau = tau_sh;

    int mycnt = 0;
    {
        int base = tid * 32;
        #pragma unroll
        for (int i = 0; i < 32; ++i)
            if (z[base + i] > tau) mycnt++;
    }
    counts[tid] = mycnt;
    __syncthreads();
    if (tid == 0) {
        int run = 0;
        for (int t = 0; t < 256; ++t) { int c = counts[t]; counts[t] = run; run += c; }
        counts[256] = run;
    }
    __syncthreads();
    const int nnz = counts[256];
    if (nnz <= SPX_CAP) {
        int off = counts[tid];
        int base = tid * 32;
        #pragma unroll
        for (int i = 0; i < 32; ++i)
            if (z[base + i] > tau) idxs[off++] = (unsigned short)(base + i);
    }
    __syncthreads();

    float4 acc = make_float4(0.f, 0.f, 0.f, 0.f);
    const float4* mem4 = (const float4*)mem;
    if (nnz <= SPX_CAP) {
        #pragma unroll 4
        for (int j = 0; j < nnz; ++j) {
            int m = idxs[j];
            float w = z[m] - tau;
            float4 v = mem4[(size_t)m * 256 + tid];
            acc.x += w * v.x; acc.y += w * v.y;
            acc.z += w * v.z; acc.w += w * v.w;
        }
    } else {
        for (int m = 0; m < NM; ++m) {
            float w = z[m] - tau;
            if (w > 0.0f) {
                float4 v = mem4[(size_t)m * 256 + tid];
                acc.x += w * v.x; acc.y += w * v.y;
                acc.z += w * v.z; acc.w += w * v.w;
            }
        }
    }
    bf16 hx, lx, hy, ly, hz, lz, hw, lw;
    bf16_split(acc.x, hx, lx); bf16_split(acc.y, hy, ly);
    bf16_split(acc.z, hz, lz); bf16_split(acc.w, hw, lw);
    bf16* ph = g_cat_hi + (size_t)row * N2D + ND + tid * 4;
    bf16* pl = g_cat_lo + (size_t)row * N2D + ND + tid * 4;
    ph[0] = hx; ph[1] = hy; ph[2] = hz; ph[3] = hw;
    pl[0] = lx; pl[1] = ly; pl[2] = lz; pl[3] = lw;
}

// ---------------------------------------------------------------
// launch
// ---------------------------------------------------------------
extern "C" void kernel_launch(void* const* d_in, const int* in_sizes, int n_in,
                              void* d_out, int out_size) {
    const float* enc  = (const float*)d_in[0];  // [4096,1024]
    const float* mem  = (const float*)d_in[1];  // [8192,1024]
    const float* fc1w = (const float*)d_in[2];  // [4096,2048]
    const float* fc1b = (const float*)d_in[3];  // [4096]
    const float* fc2w = (const float*)d_in[4];  // [1000,4096]
    const float* fc2b = (const float*)d_in[5];  // [1000]
    float* out = (float*)d_out;                 // [4096,1000]

    void *p_xinv, *p_yinv, *p_sim, *p_cath, *p_catl, *p_memh, *p_meml,
         *p_hidh, *p_hidl, *p_w1h, *p_w1l, *p_w2h, *p_w2l;
    cudaGetSymbolAddress(&p_xinv, g_xinv);
    cudaGetSymbolAddress(&p_yinv, g_yinv);
    cudaGetSymbolAddress(&p_sim,  g_sim);
    cudaGetSymbolAddress(&p_cath, g_cat_hi);
    cudaGetSymbolAddress(&p_catl, g_cat_lo);
    cudaGetSymbolAddress(&p_memh, g_mem_hi);
    cudaGetSymbolAddress(&p_meml, g_mem_lo);
    cudaGetSymbolAddress(&p_hidh, g_hid_hi);
    cudaGetSymbolAddress(&p_hidl, g_hid_lo);
    cudaGetSymbolAddress(&p_w1h,  g_w1_hi);
    cudaGetSymbolAddress(&p_w1l,  g_w1_lo);
    cudaGetSymbolAddress(&p_w2h,  g_w2_hi);
    cudaGetSymbolAddress(&p_w2l,  g_w2_lo);

    cudaFuncSetAttribute(tc_gemm<0>, cudaFuncAttributeMaxDynamicSharedMemorySize, GEMM_SMEM);
    cudaFuncSetAttribute(tc_gemm<1>, cudaFuncAttributeMaxDynamicSharedMemorySize, GEMM_SMEM);
    cudaFuncSetAttribute(tc_gemm<2>, cudaFuncAttributeMaxDynamicSharedMemorySize, GEMM_SMEM);

    // 1) norms + splits
    norm_enc_kernel<<<NB, 256>>>(enc);
    norm_mem_kernel<<<NM, 256>>>(mem);
    split_kernel<<<(int)(((size_t)NH * N2D / 4) / 256), 256>>>(
        fc1w, (bf16*)p_w1h, (bf16*)p_w1l);
    split_pad_w2_kernel<<<NOUTP, 256>>>(fc2w);

    // 2) sim = (enc @ mem^T) * xinv[row] * yinv[col]
    tc_gemm<0><<<dim3(NM / 128, NB / 128), 256, GEMM_SMEM>>>(
        NM, ND, N2D, ND, NM,
        (const bf16*)p_cath, (const bf16*)p_catl,
        (const bf16*)p_memh, (const bf16*)p_meml,
        (float*)p_sim, nullptr, nullptr,
        (const float*)p_xinv, (const float*)p_yinv, nullptr);

    // 3) sparsemax + sparse memory vector -> concat right half (bf16 split)
    sparsemax_mv_kernel<<<NB, 256>>>(mem);

    // 4) hidden = relu(concat @ fc1w^T + b) -> bf16 split stores
    tc_gemm<1><<<dim3(NH / 128, NB / 128), 256, GEMM_SMEM>>>(
        NH, N2D, N2D, N2D, NH,
        (const bf16*)p_cath, (const bf16*)p_catl,
        (const bf16*)p_w1h, (const bf16*)p_w1l,
        nullptr, (bf16*)p_hidh, (bf16*)p_hidl,
        nullptr, nullptr, fc1b);

    // 5) out = hidden @ fc2w^T + b  (padded N, store-guarded)
    tc_gemm<2><<<dim3(NOUTP / 128, NB / 128), 256, GEMM_SMEM>>>(
        NOUTP, NH, NH, NH, NOUT,
        (const bf16*)p_hidh, (const bf16*)p_hidl,
        (const bf16*)p_w2h, (const bf16*)p_w2l,
        out, nullptr, nullptr,
        nullptr, nullptr, fc2b);
}

// round 5
// speedup vs baseline: 2.7467x; 1.9675x over previous
#include <cuda_runtime.h>
#include <cuda_fp16.h>
#include <cstdint>

// Problem constants
#define NB   4096   // batch B
#define NM   8192   // memory rows M
#define ND   1024   // dim D
#define NOUT 1000   // output classes
#define NOUTP 1024  // padded output cols
#define NH   4096   // 4*D hidden
#define N2D  2048   // 2*D concat width

// -------- scratch (device globals; no allocation allowed) --------
__device__ float g_xinv[NB];
__device__ float g_yinv[NM];
__device__ float g_sim[(size_t)NB * NM];        // 128 MB
__device__ half  g_cat_hi[(size_t)NB * N2D];    // 16 MB  [enc_hi | mv_hi]
__device__ half  g_cat_lo[(size_t)NB * N2D];    // 16 MB
__device__ half  g_mem_h[(size_t)NM * ND];      // 16 MB  (B side: rounded only)
__device__ half  g_hid_hi[(size_t)NB * NH];     // 32 MB
__device__ half  g_hid_lo[(size_t)NB * NH];     // 32 MB
__device__ half  g_w1_h[(size_t)NH * N2D];      // 16 MB
__device__ half  g_w2_h[(size_t)NOUTP * NH];    // 8 MB (padded)

// ---------------------------------------------------------------
// helpers
// ---------------------------------------------------------------
__device__ __forceinline__ uint32_t cvta_smem(const void* p) {
    uint32_t a;
    asm("{ .reg .u64 t; cvta.to.shared.u64 t, %1; cvt.u32.u64 %0, t; }"
        : "=r"(a) : "l"(p));
    return a;
}

__device__ __forceinline__ void cp16(uint32_t dst, const void* src) {
    asm volatile("cp.async.cg.shared.global [%0], [%1], 16;" :: "r"(dst), "l"(src));
}

__device__ __forceinline__ void mma_fp16(float* d, const uint32_t* a, const uint32_t* b) {
    asm volatile(
        "mma.sync.aligned.m16n8k16.row.col.f32.f16.f16.f32 "
        "{%0,%1,%2,%3}, {%4,%5,%6,%7}, {%8,%9}, {%0,%1,%2,%3};"
        : "+f"(d[0]), "+f"(d[1]), "+f"(d[2]), "+f"(d[3])
        : "r"(a[0]), "r"(a[1]), "r"(a[2]), "r"(a[3]), "r"(b[0]), "r"(b[1]));
}

__device__ __forceinline__ void ldsm_x4(uint32_t* r, uint32_t addr) {
    asm volatile("ldmatrix.sync.aligned.m8n8.x4.shared.b16 {%0,%1,%2,%3}, [%4];"
                 : "=r"(r[0]), "=r"(r[1]), "=r"(r[2]), "=r"(r[3]) : "r"(addr));
}

__device__ __forceinline__ void ldsm_x2(uint32_t* r, uint32_t addr) {
    asm volatile("ldmatrix.sync.aligned.m8n8.x2.shared.b16 {%0,%1}, [%2];"
                 : "=r"(r[0]), "=r"(r[1]) : "r"(addr));
}

__device__ __forceinline__ void fp16_split(float v, half& h, half& l) {
    h = __float2half_rn(v);
    l = __float2half_rn(v - __half2float(h));
}

// ---------------------------------------------------------------
// block reduce (256 threads)
// ---------------------------------------------------------------
__device__ __forceinline__ float blockReduceSum256(float v, float* red) {
    __syncthreads();
    #pragma unroll
    for (int o = 16; o > 0; o >>= 1) v += __shfl_down_sync(0xffffffffu, v, o);
    int warp = threadIdx.x >> 5, lane = threadIdx.x & 31;
    if (lane == 0) red[warp] = v;
    __syncthreads();
    if (warp == 0) {
        v = (lane < 8) ? red[lane] : 0.0f;
        #pragma unroll
        for (int o = 4; o > 0; o >>= 1) v += __shfl_down_sync(0xffffffffu, v, o);
        if (lane == 0) red[0] = v;
    }
    __syncthreads();
    return red[0];
}

// ---------------------------------------------------------------
// encoder: 1/||x||, fp16 split of raw enc -> concat left half
// ---------------------------------------------------------------
__global__ __launch_bounds__(256) void norm_enc_kernel(const float* __restrict__ enc) {
    __shared__ float red[8];
    int row = blockIdx.x, tid = threadIdx.x;
    float4 v = ((const float4*)(enc + (size_t)row * ND))[tid];
    float s = v.x*v.x + v.y*v.y + v.z*v.z + v.w*v.w;
    s = blockReduceSum256(s, red);
    if (tid == 0) g_xinv[row] = rsqrtf(s + 1e-6f);
    half hx, lx, hy, ly, hz, lz, hw, lw;
    fp16_split(v.x, hx, lx); fp16_split(v.y, hy, ly);
    fp16_split(v.z, hz, lz); fp16_split(v.w, hw, lw);
    half* ph = g_cat_hi + (size_t)row * N2D + tid * 4;
    half* pl = g_cat_lo + (size_t)row * N2D + tid * 4;
    ph[0] = hx; ph[1] = hy; ph[2] = hz; ph[3] = hw;
    pl[0] = lx; pl[1] = ly; pl[2] = lz; pl[3] = lw;
}

// ---------------------------------------------------------------
// memory rows: 1/||y|| + fp16 round (B side, no lo needed)
// ---------------------------------------------------------------
__global__ __launch_bounds__(256) void norm_mem_kernel(const float* __restrict__ mem) {
    __shared__ float red[8];
    int row = blockIdx.x, tid = threadIdx.x;
    float4 v = ((const float4*)(mem + (size_t)row * ND))[tid];
    float s = v.x*v.x + v.y*v.y + v.z*v.z + v.w*v.w;
    s = blockReduceSum256(s, red);
    if (tid == 0) g_yinv[row] = rsqrtf(s + 1e-6f);
    half* ph = g_mem_h + (size_t)row * ND + tid * 4;
    ph[0] = __float2half_rn(v.x); ph[1] = __float2half_rn(v.y);
    ph[2] = __float2half_rn(v.z); ph[3] = __float2half_rn(v.w);
}

// ---------------------------------------------------------------
// fp32 -> fp16 round (weights)
// ---------------------------------------------------------------
__global__ __launch_bounds__(256) void round_kernel(
    const float* __restrict__ src, half* __restrict__ dst) {
    size_t i = (size_t)blockIdx.x * 256 + threadIdx.x;
    float4 v = ((const float4*)src)[i];
    half* p = dst + i * 4;
    p[0] = __float2half_rn(v.x); p[1] = __float2half_rn(v.y);
    p[2] = __float2half_rn(v.z); p[3] = __float2half_rn(v.w);
}

// fc2 weights: round + zero-pad rows [1000,1024)
__global__ __launch_bounds__(256) void round_pad_w2_kernel(const float* __restrict__ src) {
    int row = blockIdx.x, tid = threadIdx.x;  // 1024 rows x 4096 cols
    #pragma unroll
    for (int lq = 0; lq < 4; ++lq) {
        int idx = tid + 256 * lq;
        float4 v = make_float4(0.f, 0.f, 0.f, 0.f);
        if (row < NOUT) v = ((const float4*)(src + (size_t)row * NH))[idx];
        half* p = g_w2_h + (size_t)row * NH + idx * 4;
        p[0] = __float2half_rn(v.x); p[1] = __float2half_rn(v.y);
        p[2] = __float2half_rn(v.z); p[3] = __float2half_rn(v.w);
    }
}

// ---------------------------------------------------------------
// fp16 2-pass split GEMM (mma.sync.m16n8k16 + ldmatrix):
//   C[M,N] = (Ah+Al)[M,K] @ Bh[N,K]^T, fp32 accum
// 128x128 CTA tile, BK=64, stage={Ah,Al,B}, 3-stage cp.async pipeline,
// 256 threads (8 warps 2x4).  B tile reused for both A passes.
// EPI: 0 = sim   (v * xinv[row] * yinv[col], fp32 store)
//      1 = fc1   (relu(v+bias) -> fp16 split stores)
//      2 = fc2   (v+bias, fp32 store guarded col<Nout, row stride Nout)
// ---------------------------------------------------------------
#define BKE     64                       // K elems per chunk
#define ROW_B   144                      // smem row stride bytes (128 + 16 pad)
#define AT_B    (128 * ROW_B)            // 18432 bytes per tile
#define STAGE_B (3 * AT_B)               // 55296 (Ah | Al | B)
#define NSTAGE  3
#define GEMM_SMEM (NSTAGE * STAGE_B)     // 165888

template<int EPI>
__global__ __launch_bounds__(256, 1) void tc_gemm(
    int N, int K, int lda, int ldb, int Nout,
    const half* __restrict__ A0, const half* __restrict__ A1,
    const half* __restrict__ B0,
    float* __restrict__ C, half* __restrict__ Ch, half* __restrict__ Cl,
    const float* __restrict__ xinv, const float* __restrict__ yinv,
    const float* __restrict__ bias)
{
    extern __shared__ __align__(1024) char smraw[];
    const uint32_t smemU = cvta_smem(smraw);

    const int tid  = threadIdx.x;
    const int lane = tid & 31;
    const int wid  = tid >> 5;
    const int wm   = wid & 1;          // 0..1  (64-row block)
    const int wn   = wid >> 1;         // 0..3  (32-col block)
    const int row0 = blockIdx.y * 128;
    const int col0 = blockIdx.x * 128;

    const int nkc = K / BKE;

    // global->smem mapping: thread t: row = t>>1, half64 = t&1, 4 x cp16
    const int ldr = tid >> 1;
    const int ldh = tid & 1;
    const uint32_t sBase = smemU + ldr * ROW_B + ldh * 64;

    auto do_load = [&](int ck, int s) {
        const half* ga = A0 + (size_t)(row0 + ldr) * lda + ck * BKE + ldh * 32;
        const half* gl = A1 + (size_t)(row0 + ldr) * lda + ck * BKE + ldh * 32;
        const half* gb = B0 + (size_t)(col0 + ldr) * ldb + ck * BKE + ldh * 32;
        const uint32_t so = sBase + s * STAGE_B;
        #pragma unroll
        for (int i = 0; i < 4; ++i) {
            cp16(so + i * 16, ga + i * 8);
            cp16(so + AT_B + i * 16, gl + i * 8);
            cp16(so + 2 * AT_B + i * 16, gb + i * 8);
        }
    };

    float acc[4][4][4];
    #pragma unroll
    for (int mt = 0; mt < 4; ++mt)
        #pragma unroll
        for (int nt = 0; nt < 4; ++nt)
            #pragma unroll
            for (int c = 0; c < 4; ++c) acc[mt][nt][c] = 0.0f;

    do_load(0, 0);
    asm volatile("cp.async.commit_group;" ::: "memory");
    do_load(1, 1);
    asm volatile("cp.async.commit_group;" ::: "memory");

    // ldmatrix lane bases
    const uint32_t aFragBase = smemU + (wm * 64 + (lane & 15)) * ROW_B + (lane >> 4) * 16;
    const uint32_t bFragBase = smemU + 2 * AT_B +
                               (wn * 32 + (lane & 7)) * ROW_B + ((lane >> 3) & 1) * 16;

    for (int it = 0; it < nkc; ++it) {
        if (it + 2 < nkc) {
            asm volatile("cp.async.wait_group 1;" ::: "memory");
        } else {
            asm volatile("cp.async.wait_group 0;" ::: "memory");
        }
        __syncthreads();
        if (it + 2 < nkc) {
            do_load(it + 2, (it + 2) % NSTAGE);
            asm volatile("cp.async.commit_group;" ::: "memory");
        }

        const uint32_t so = (it % NSTAGE) * STAGE_B;

        #pragma unroll
        for (int ks = 0; ks < 4; ++ks) {
            const uint32_t ko = ks * 32;
            uint32_t bfr[4][2];
            #pragma unroll
            for (int nt = 0; nt < 4; ++nt)
                ldsm_x2(bfr[nt], bFragBase + so + nt * (8 * ROW_B) + ko);

            uint32_t afr[4][4];
            #pragma unroll
            for (int mt = 0; mt < 4; ++mt)
                ldsm_x4(afr[mt], aFragBase + so + mt * (16 * ROW_B) + ko);
            #pragma unroll
            for (int mt = 0; mt < 4; ++mt)
                #pragma unroll
                for (int nt = 0; nt < 4; ++nt)
                    mma_fp16(acc[mt][nt], afr[mt], bfr[nt]);

            #pragma unroll
            for (int mt = 0; mt < 4; ++mt)
                ldsm_x4(afr[mt], aFragBase + so + AT_B + mt * (16 * ROW_B) + ko);
            #pragma unroll
            for (int mt = 0; mt < 4; ++mt)
                #pragma unroll
                for (int nt = 0; nt < 4; ++nt)
                    mma_fp16(acc[mt][nt], afr[mt], bfr[nt]);
        }
        __syncthreads();
    }

    // epilogue
    const int r = lane >> 2;
    const int q = lane & 3;
    #pragma unroll
    for (int mt = 0; mt < 4; ++mt) {
        const int gr0 = row0 + wm * 64 + mt * 16 + r;
        #pragma unroll
        for (int half_ = 0; half_ < 2; ++half_) {
            const int gr = gr0 + half_ * 8;
            float xr = 0.0f;
            if (EPI == 0) xr = xinv[gr];
            #pragma unroll
            for (int nt = 0; nt < 4; ++nt) {
                const int gc = col0 + wn * 32 + nt * 8 + q * 2;
                float v0 = acc[mt][nt][half_ * 2 + 0];
                float v1 = acc[mt][nt][half_ * 2 + 1];
                if (EPI == 0) {
                    float2 o = make_float2(v0 * xr * yinv[gc], v1 * xr * yinv[gc + 1]);
                    *(float2*)(C + (size_t)gr * N + gc) = o;
                } else if (EPI == 1) {
                    v0 = fmaxf(v0 + bias[gc], 0.0f);
                    v1 = fmaxf(v1 + bias[gc + 1], 0.0f);
                    half h0, l0, h1, l1;
                    fp16_split(v0, h0, l0);
                    fp16_split(v1, h1, l1);
                    __half2 hh; hh.x = h0; hh.y = h1;
                    __half2 ll; ll.x = l0; ll.y = l1;
                    *(__half2*)(Ch + (size_t)gr * N + gc) = hh;
                    *(__half2*)(Cl + (size_t)gr * N + gc) = ll;
                } else {
                    if (gc < Nout) {
                        float2 o = make_float2(v0 + bias[gc], v1 + bias[gc + 1]);
                        *(float2*)(C + (size_t)gr * Nout + gc) = o;
                    }
                }
            }
        }
    }
}

// ---------------------------------------------------------------
// Fused sparsemax (Michelot, sort-free, register-resident) + sparse
// memory-vector gather.  Writes fp16 split mv into concat right half.
// ---------------------------------------------------------------
#define SPX_CAP 4096
__global__ __launch_bounds__(256) void sparsemax_mv_kernel(const float* __restrict__ mem) {
    __shared__ float z[NM];                  // 32 KB
    __shared__ unsigned short idxs[SPX_CAP]; // 8 KB
    __shared__ float redS[8];
    __shared__ float redC[8];
    __shared__ int   counts[257];
    __shared__ float tau_sh;
    __shared__ int   cprev_sh;
    __shared__ int   done_sh;

    const int row = blockIdx.x;
    const int tid = threadIdx.x;

    // load sim row into regs + smem
    float4 zr[8];
    const float4* src = (const float4*)(g_sim + (size_t)row * NM);
    #pragma unroll
    for (int l = 0; l < 8; ++l) {
        zr[l] = src[tid + l * 256];
        ((float4*)z)[tid + l * 256] = zr[l];
    }
    __syncthreads();

    {
        float s = 0.0f;
        #pragma unroll
        for (int l = 0; l < 8; ++l)
            s += zr[l].x + zr[l].y + zr[l].z + zr[l].w;
        s = blockReduceSum256(s, redS);
        if (tid == 0) {
            tau_sh = (s - 1.0f) / (float)NM;
            cprev_sh = NM;
            done_sh = 0;
        }
        __syncthreads();
    }

    for (int it = 0; it < 64; ++it) {
        float tau = tau_sh;
        float ls = 0.0f, lc = 0.0f;
        #pragma unroll
        for (int l = 0; l < 8; ++l) {
            if (zr[l].x > tau) { ls += zr[l].x; lc += 1.0f; }
            if (zr[l].y > tau) { ls += zr[l].y; lc += 1.0f; }
            if (zr[l].z > tau) { ls += zr[l].z; lc += 1.0f; }
            if (zr[l].w > tau) { ls += zr[l].w; lc += 1.0f; }
        }
        #pragma unroll
        for (int o = 16; o > 0; o >>= 1) {
            ls += __shfl_down_sync(0xffffffffu, ls, o);
            lc += __shfl_down_sync(0xffffffffu, lc, o);
        }
        int warp = tid >> 5, lane = tid & 31;
        if (lane == 0) { redS[warp] = ls; redC[warp] = lc; }
        __syncthreads();
        if (tid == 0) {
            float S = 0.0f, Cc = 0.0f;
            #pragma unroll
            for (int w = 0; w < 8; ++w) { S += redS[w]; Cc += redC[w]; }
            int c = (int)(Cc + 0.5f);
            if (c == cprev_sh || c <= 0) done_sh = 1;
            else { cprev_sh = c; tau_sh = (S - 1.0f) / (float)c; }
        }
        __syncthreads();
        if (done_sh) break;
    }
    const float tau = tau_sh;

    // deterministic compaction (thread owns its 8 float4s)
    int mycnt = 0;
    #pragma unroll
    for (int l = 0; l < 8; ++l) {
        if (zr[l].x > tau) mycnt++;
        if (zr[l].y > tau) mycnt++;
        if (zr[l].z > tau) mycnt++;
        if (zr[l].w > tau) mycnt++;
    }
    counts[tid] = mycnt;
    __syncthreads();
    if (tid == 0) {
        int run = 0;
        for (int t = 0; t < 256; ++t) { int c = counts[t]; counts[t] = run; run += c; }
        counts[256] = run;
    }
    __syncthreads();
    const int nnz = counts[256];
    if (nnz <= SPX_CAP) {
        int off = counts[tid];
        #pragma unroll
        for (int l = 0; l < 8; ++l) {
            int base = 4 * (tid + l * 256);
            if (zr[l].x > tau) idxs[off++] = (unsigned short)(base + 0);
            if (zr[l].y > tau) idxs[off++] = (unsigned short)(base + 1);
            if (zr[l].z > tau) idxs[off++] = (unsigned short)(base + 2);
            if (zr[l].w > tau) idxs[off++] = (unsigned short)(base + 3);
        }
    }
    __syncthreads();

    float4 acc = make_float4(0.f, 0.f, 0.f, 0.f);
    const float4* mem4 = (const float4*)mem;
    if (nnz <= SPX_CAP) {
        #pragma unroll 4
        for (int j = 0; j < nnz; ++j) {
            int m = idxs[j];
            float w = z[m] - tau;
            float4 v = mem4[(size_t)m * 256 + tid];
            acc.x += w * v.x; acc.y += w * v.y;
            acc.z += w * v.z; acc.w += w * v.w;
        }
    } else {
        for (int m = 0; m < NM; ++m) {
            float w = z[m] - tau;
            if (w > 0.0f) {
                float4 v = mem4[(size_t)m * 256 + tid];
                acc.x += w * v.x; acc.y += w * v.y;
                acc.z += w * v.z; acc.w += w * v.w;
            }
        }
    }
    half hx, lx, hy, ly, hz, lz, hw, lw;
    fp16_split(acc.x, hx, lx); fp16_split(acc.y, hy, ly);
    fp16_split(acc.z, hz, lz); fp16_split(acc.w, hw, lw);
    half* ph = g_cat_hi + (size_t)row * N2D + ND + tid * 4;
    half* pl = g_cat_lo + (size_t)row * N2D + ND + tid * 4;
    ph[0] = hx; ph[1] = hy; ph[2] = hz; ph[3] = hw;
    pl[0] = lx; pl[1] = ly; pl[2] = lz; pl[3] = lw;
}

// ---------------------------------------------------------------
// launch
// ---------------------------------------------------------------
extern "C" void kernel_launch(void* const* d_in, const int* in_sizes, int n_in,
                              void* d_out, int out_size) {
    const float* enc  = (const float*)d_in[0];  // [4096,1024]
    const float* mem  = (const float*)d_in[1];  // [8192,1024]
    const float* fc1w = (const float*)d_in[2];  // [4096,2048]
    const float* fc1b = (const float*)d_in[3];  // [4096]
    const float* fc2w = (const float*)d_in[4];  // [1000,4096]
    const float* fc2b = (const float*)d_in[5];  // [1000]
    float* out = (float*)d_out;                 // [4096,1000]

    void *p_xinv, *p_yinv, *p_sim, *p_cath, *p_catl, *p_memh,
         *p_hidh, *p_hidl, *p_w1h, *p_w2h;
    cudaGetSymbolAddress(&p_xinv, g_xinv);
    cudaGetSymbolAddress(&p_yinv, g_yinv);
    cudaGetSymbolAddress(&p_sim,  g_sim);
    cudaGetSymbolAddress(&p_cath, g_cat_hi);
    cudaGetSymbolAddress(&p_catl, g_cat_lo);
    cudaGetSymbolAddress(&p_memh, g_mem_h);
    cudaGetSymbolAddress(&p_hidh, g_hid_hi);
    cudaGetSymbolAddress(&p_hidl, g_hid_lo);
    cudaGetSymbolAddress(&p_w1h,  g_w1_h);
    cudaGetSymbolAddress(&p_w2h,  g_w2_h);

    cudaFuncSetAttribute(tc_gemm<0>, cudaFuncAttributeMaxDynamicSharedMemorySize, GEMM_SMEM);
    cudaFuncSetAttribute(tc_gemm<1>, cudaFuncAttributeMaxDynamicSharedMemorySize, GEMM_SMEM);
    cudaFuncSetAttribute(tc_gemm<2>, cudaFuncAttributeMaxDynamicSharedMemorySize, GEMM_SMEM);

    // 1) norms + rounds/splits
    norm_enc_kernel<<<NB, 256>>>(enc);
    norm_mem_kernel<<<NM, 256>>>(mem);
    round_kernel<<<(int)(((size_t)NH * N2D / 4) / 256), 256>>>(fc1w, (half*)p_w1h);
    round_pad_w2_kernel<<<NOUTP, 256>>>(fc2w);

    // 2) sim = (enc @ mem^T) * xinv[row] * yinv[col]
    tc_gemm<0><<<dim3(NM / 128, NB / 128), 256, GEMM_SMEM>>>(
        NM, ND, N2D, ND, NM,
        (const half*)p_cath, (const half*)p_catl, (const half*)p_memh,
        (float*)p_sim, nullptr, nullptr,
        (const float*)p_xinv, (const float*)p_yinv, nullptr);

    // 3) sparsemax + sparse memory vector -> concat right half (fp16 split)
    sparsemax_mv_kernel<<<NB, 256>>>(mem);

    // 4) hidden = relu(concat @ fc1w^T + b) -> fp16 split stores
    tc_gemm<1><<<dim3(NH / 128, NB / 128), 256, GEMM_SMEM>>>(
        NH, N2D, N2D, N2D, NH,
        (const half*)p_cath, (const half*)p_catl, (const half*)p_w1h,
        nullptr, (half*)p_hidh, (half*)p_hidl,
        nullptr, nullptr, fc1b);

    // 5) out = hidden @ fc2w^T + b  (padded N, store-guarded)
    tc_gemm<2><<<dim3(NOUTP / 128, NB / 128), 256, GEMM_SMEM>>>(
        NOUTP, NH, NH, NH, NOUT,
        (const half*)p_hidh, (const half*)p_hidl, (const half*)p_w2h,
        out, nullptr, nullptr,
        nullptr, nullptr, fc2b);
}

// round 7
// speedup vs baseline: 3.3177x; 1.2078x over previous
#include <cuda_runtime.h>
#include <cuda_fp16.h>
#include <cstdint>

// Problem constants
#define NB   4096   // batch B
#define NM   8192   // memory rows M
#define ND   1024   // dim D
#define NOUT 1000   // output classes
#define NOUTP 1024  // padded output cols
#define NH   4096   // 4*D hidden
#define N2D  2048   // 2*D concat width

// -------- scratch (device globals; no allocation allowed) --------
__device__ float g_xinv[NB];
__device__ float g_yinv[NM];
__device__ float g_sim[(size_t)NB * NM];        // 128 MB
__device__ half  g_cat_hi[(size_t)NB * N2D];    // 16 MB  [enc_hi | mv_hi]
__device__ half  g_cat_lo[(size_t)NB * N2D];    // 16 MB
__device__ half  g_mem_h[(size_t)NM * ND];      // 16 MB  (B side: rounded only)
__device__ half  g_hid_hi[(size_t)NB * NH];     // 32 MB
__device__ half  g_hid_lo[(size_t)NB * NH];     // 32 MB
__device__ half  g_w1_h[(size_t)NH * N2D];      // 16 MB
__device__ half  g_w2_h[(size_t)NOUTP * NH];    // 8 MB (padded)

// ---------------------------------------------------------------
// helpers
// ---------------------------------------------------------------
__device__ __forceinline__ uint32_t cvta_smem(const void* p) {
    uint32_t a;
    asm("{ .reg .u64 t; cvta.to.shared.u64 t, %1; cvt.u32.u64 %0, t; }"
        : "=r"(a) : "l"(p));
    return a;
}

__device__ __forceinline__ void cp16(uint32_t dst, const void* src) {
    asm volatile("cp.async.cg.shared.global [%0], [%1], 16;" :: "r"(dst), "l"(src));
}

__device__ __forceinline__ void mma_fp16(float* d, const uint32_t* a, const uint32_t* b) {
    asm volatile(
        "mma.sync.aligned.m16n8k16.row.col.f32.f16.f16.f32 "
        "{%0,%1,%2,%3}, {%4,%5,%6,%7}, {%8,%9}, {%0,%1,%2,%3};"
        : "+f"(d[0]), "+f"(d[1]), "+f"(d[2]), "+f"(d[3])
        : "r"(a[0]), "r"(a[1]), "r"(a[2]), "r"(a[3]), "r"(b[0]), "r"(b[1]));
}

__device__ __forceinline__ void ldsm_x4(uint32_t* r, uint32_t addr) {
    asm volatile("ldmatrix.sync.aligned.m8n8.x4.shared.b16 {%0,%1,%2,%3}, [%4];"
                 : "=r"(r[0]), "=r"(r[1]), "=r"(r[2]), "=r"(r[3]) : "r"(addr));
}

__device__ __forceinline__ void ldsm_x2(uint32_t* r, uint32_t addr) {
    asm volatile("ldmatrix.sync.aligned.m8n8.x2.shared.b16 {%0,%1}, [%2];"
                 : "=r"(r[0]), "=r"(r[1]) : "r"(addr));
}

__device__ __forceinline__ void fp16_split(float v, half& h, half& l) {
    h = __float2half_rn(v);
    l = __float2half_rn(v - __half2float(h));
}

// ---------------------------------------------------------------
// block reduce (256 threads)
// ---------------------------------------------------------------
__device__ __forceinline__ float blockReduceSum256(float v, float* red) {
    __syncthreads();
    #pragma unroll
    for (int o = 16; o > 0; o >>= 1) v += __shfl_down_sync(0xffffffffu, v, o);
    int warp = threadIdx.x >> 5, lane = threadIdx.x & 31;
    if (lane == 0) red[warp] = v;
    __syncthreads();
    if (warp == 0) {
        v = (lane < 8) ? red[lane] : 0.0f;
        #pragma unroll
        for (int o = 4; o > 0; o >>= 1) v += __shfl_down_sync(0xffffffffu, v, o);
        if (lane == 0) red[0] = v;
    }
    __syncthreads();
    return red[0];
}

// ---------------------------------------------------------------
// encoder: 1/||x||, fp16 split of raw enc -> concat left half
// ---------------------------------------------------------------
__global__ __launch_bounds__(256) void norm_enc_kernel(const float* __restrict__ enc) {
    __shared__ float red[8];
    int row = blockIdx.x, tid = threadIdx.x;
    float4 v = ((const float4*)(enc + (size_t)row * ND))[tid];
    float s = v.x*v.x + v.y*v.y + v.z*v.z + v.w*v.w;
    s = blockReduceSum256(s, red);
    if (tid == 0) g_xinv[row] = rsqrtf(s + 1e-6f);
    half hx, lx, hy, ly, hz, lz, hw, lw;
    fp16_split(v.x, hx, lx); fp16_split(v.y, hy, ly);
    fp16_split(v.z, hz, lz); fp16_split(v.w, hw, lw);
    half* ph = g_cat_hi + (size_t)row * N2D + tid * 4;
    half* pl = g_cat_lo + (size_t)row * N2D + tid * 4;
    ph[0] = hx; ph[1] = hy; ph[2] = hz; ph[3] = hw;
    pl[0] = lx; pl[1] = ly; pl[2] = lz; pl[3] = lw;
}

// ---------------------------------------------------------------
// memory rows: 1/||y|| + fp16 round (B side)
// ---------------------------------------------------------------
__global__ __launch_bounds__(256) void norm_mem_kernel(const float* __restrict__ mem) {
    __shared__ float red[8];
    int row = blockIdx.x, tid = threadIdx.x;
    float4 v = ((const float4*)(mem + (size_t)row * ND))[tid];
    float s = v.x*v.x + v.y*v.y + v.z*v.z + v.w*v.w;
    s = blockReduceSum256(s, red);
    if (tid == 0) g_yinv[row] = rsqrtf(s + 1e-6f);
    half* ph = g_mem_h + (size_t)row * ND + tid * 4;
    ph[0] = __float2half_rn(v.x); ph[1] = __float2half_rn(v.y);
    ph[2] = __float2half_rn(v.z); ph[3] = __float2half_rn(v.w);
}

// ---------------------------------------------------------------
// fp32 -> fp16 round (weights)
// ---------------------------------------------------------------
__global__ __launch_bounds__(256) void round_kernel(
    const float* __restrict__ src, half* __restrict__ dst) {
    size_t i = (size_t)blockIdx.x * 256 + threadIdx.x;
    float4 v = ((const float4*)src)[i];
    half* p = dst + i * 4;
    p[0] = __float2half_rn(v.x); p[1] = __float2half_rn(v.y);
    p[2] = __float2half_rn(v.z); p[3] = __float2half_rn(v.w);
}

// fc2 weights: round + zero-pad rows [1000,1024)
__global__ __launch_bounds__(256) void round_pad_w2_kernel(const float* __restrict__ src) {
    int row = blockIdx.x, tid = threadIdx.x;  // 1024 rows x 4096 cols
    #pragma unroll
    for (int lq = 0; lq < 4; ++lq) {
        int idx = tid + 256 * lq;
        float4 v = make_float4(0.f, 0.f, 0.f, 0.f);
        if (row < NOUT) v = ((const float4*)(src + (size_t)row * NH))[idx];
        half* p = g_w2_h + (size_t)row * NH + idx * 4;
        p[0] = __float2half_rn(v.x); p[1] = __float2half_rn(v.y);
        p[2] = __float2half_rn(v.z); p[3] = __float2half_rn(v.w);
    }
}

// ---------------------------------------------------------------
// fp16 split GEMM (mma.sync.m16n8k16 + ldmatrix):
//   C[M,N] = (Ah [+ Al])[M,K] @ Bh[N,K]^T, fp32 accum
// 128x256 CTA tile, BK=64, stage={Ah,Al,B}, 3-stage cp.async pipeline,
// 256 threads (8 warps 2x4, 64x64 warp tiles). B tile reused across passes.
// PASSES: 1 = Ah only (sim), 2 = Ah+Al (fc1/fc2)
// EPI: 0 = sim   (v * xinv[row] * yinv[col], fp32 store)
//      1 = fc1   (relu(v+bias) -> fp16 split stores)
//      2 = fc2   (v+bias, fp32 store guarded col<Nout, row stride Nout)
// ---------------------------------------------------------------
#define BKE     64                       // K elems per chunk
#define ROW_B   144                      // smem row stride bytes (128 + 16 pad)
#define A_T     (128 * ROW_B)            // 18432 bytes (A tile)
#define B_T     (256 * ROW_B)            // 36864 bytes (B tile)
#define STAGE_B (2 * A_T + B_T)          // 73728 (Ah | Al | B)
#define NSTAGE  3
#define GEMM_SMEM (NSTAGE * STAGE_B)     // 221184

template<int PASSES, int EPI>
__global__ __launch_bounds__(256, 1) void tc_gemm(
    int N, int K, int lda, int ldb, int Nout,
    const half* __restrict__ A0, const half* __restrict__ A1,
    const half* __restrict__ B0,
    float* __restrict__ C, half* __restrict__ Ch, half* __restrict__ Cl,
    const float* __restrict__ xinv, const float* __restrict__ yinv,
    const float* __restrict__ bias)
{
    extern __shared__ __align__(1024) char smraw[];
    const uint32_t smemU = cvta_smem(smraw);

    const int tid  = threadIdx.x;
    const int lane = tid & 31;
    const int wid  = tid >> 5;
    const int wm   = wid & 1;          // 0..1  (64-row block)
    const int wn   = wid >> 1;         // 0..3  (64-col block)
    const int row0 = blockIdx.y * 128;
    const int col0 = blockIdx.x * 256;

    const int nkc = K / BKE;

    // global->smem: A: 2 threads/row (64B each); B: 1 thread/row (128B)
    const int ldr = tid >> 1;
    const int ldh = tid & 1;
    const uint32_t aBase = smemU + ldr * ROW_B + ldh * 64;
    const uint32_t bBase = smemU + 2 * A_T + tid * ROW_B;

    auto do_load = [&](int ck, int s) {
        const uint32_t so = s * STAGE_B;
        const half* ga = A0 + (size_t)(row0 + ldr) * lda + ck * BKE + ldh * 32;
        #pragma unroll
        for (int i = 0; i < 4; ++i) cp16(aBase + so + i * 16, ga + i * 8);
        if (PASSES == 2) {
            const half* gl = A1 + (size_t)(row0 + ldr) * lda + ck * BKE + ldh * 32;
            #pragma unroll
            for (int i = 0; i < 4; ++i) cp16(aBase + so + A_T + i * 16, gl + i * 8);
        }
        const half* gb = B0 + (size_t)(col0 + tid) * ldb + ck * BKE;
        #pragma unroll
        for (int i = 0; i < 8; ++i) cp16(bBase + so + i * 16, gb + i * 8);
    };

    float acc[4][8][4];
    #pragma unroll
    for (int mt = 0; mt < 4; ++mt)
        #pragma unroll
        for (int nt = 0; nt < 8; ++nt)
            #pragma unroll
            for (int c = 0; c < 4; ++c) acc[mt][nt][c] = 0.0f;

    do_load(0, 0);
    asm volatile("cp.async.commit_group;" ::: "memory");
    do_load(1, 1);
    asm volatile("cp.async.commit_group;" ::: "memory");

    // ldmatrix lane bases
    const uint32_t aFragBase = smemU + (wm * 64 + (lane & 15)) * ROW_B + (lane >> 4) * 16;
    const uint32_t bFragBase = smemU + 2 * A_T +
                               (wn * 64 + (lane & 7)) * ROW_B + ((lane >> 3) & 1) * 16;

    for (int it = 0; it < nkc; ++it) {
        if (it + 2 < nkc) {
            asm volatile("cp.async.wait_group 1;" ::: "memory");
        } else {
            asm volatile("cp.async.wait_group 0;" ::: "memory");
        }
        __syncthreads();
        if (it + 2 < nkc) {
            do_load(it + 2, (it + 2) % NSTAGE);
            asm volatile("cp.async.commit_group;" ::: "memory");
        }

        const uint32_t so = (it % NSTAGE) * STAGE_B;

        #pragma unroll
        for (int ks = 0; ks < 4; ++ks) {
            const uint32_t ko = ks * 32;
            uint32_t bfr[8][2];
            #pragma unroll
            for (int nt = 0; nt < 8; ++nt)
                ldsm_x2(bfr[nt], bFragBase + so + nt * (8 * ROW_B) + ko);

            uint32_t afr[4][4];
            #pragma unroll
            for (int mt = 0; mt < 4; ++mt)
                ldsm_x4(afr[mt], aFragBase + so + mt * (16 * ROW_B) + ko);
            #pragma unroll
            for (int mt = 0; mt < 4; ++mt)
                #pragma unroll
                for (int nt = 0; nt < 8; ++nt)
                    mma_fp16(acc[mt][nt], afr[mt], bfr[nt]);

            if (PASSES == 2) {
                #pragma unroll
                for (int mt = 0; mt < 4; ++mt)
                    ldsm_x4(afr[mt], aFragBase + so + A_T + mt * (16 * ROW_B) + ko);
                #pragma unroll
                for (int mt = 0; mt < 4; ++mt)
                    #pragma unroll
                    for (int nt = 0; nt < 8; ++nt)
                        mma_fp16(acc[mt][nt], afr[mt], bfr[nt]);
            }
        }
        __syncthreads();
    }

    // epilogue
    const int r = lane >> 2;
    const int q = lane & 3;
    #pragma unroll
    for (int mt = 0; mt < 4; ++mt) {
        const int gr0 = row0 + wm * 64 + mt * 16 + r;
        #pragma unroll
        for (int half_ = 0; half_ < 2; ++half_) {
            const int gr = gr0 + half_ * 8;
            float xr = 0.0f;
            if (EPI == 0) xr = xinv[gr];
            #pragma unroll
            for (int nt = 0; nt < 8; ++nt) {
                const int gc = col0 + wn * 64 + nt * 8 + q * 2;
                float v0 = acc[mt][nt][half_ * 2 + 0];
                float v1 = acc[mt][nt][half_ * 2 + 1];
                if (EPI == 0) {
                    float2 o = make_float2(v0 * xr * yinv[gc], v1 * xr * yinv[gc + 1]);
                    *(float2*)(C + (size_t)gr * N + gc) = o;
                } else if (EPI == 1) {
                    v0 = fmaxf(v0 + bias[gc], 0.0f);
                    v1 = fmaxf(v1 + bias[gc + 1], 0.0f);
                    half h0, l0, h1, l1;
                    fp16_split(v0, h0, l0);
                    fp16_split(v1, h1, l1);
                    __half2 hh; hh.x = h0; hh.y = h1;
                    __half2 ll; ll.x = l0; ll.y = l1;
                    *(__half2*)(Ch + (size_t)gr * N + gc) = hh;
                    *(__half2*)(Cl + (size_t)gr * N + gc) = ll;
                } else {
                    if (gc < Nout) {
                        float2 o = make_float2(v0 + bias[gc], v1 + bias[gc + 1]);
                        *(float2*)(C + (size_t)gr * Nout + gc) = o;
                    }
                }
            }
        }
    }
}

// ---------------------------------------------------------------
// Fused sparsemax (Michelot, sort-free, register-resident) + sparse
// memory-vector gather.  Writes fp16 split mv into concat right half.
// ---------------------------------------------------------------
#define SPX_CAP 4096
__global__ __launch_bounds__(256) void sparsemax_mv_kernel(const float* __restrict__ mem) {
    __shared__ float z[NM];                  // 32 KB
    __shared__ unsigned short idxs[SPX_CAP]; // 8 KB
    __shared__ float redS[8];
    __shared__ float redC[8];
    __shared__ int   counts[257];
    __shared__ float tau_sh;
    __shared__ int   cprev_sh;
    __shared__ int   done_sh;

    const int row = blockIdx.x;
    const int tid = threadIdx.x;

    // load sim row into regs + smem
    float4 zr[8];
    const float4* src = (const float4*)(g_sim + (size_t)row * NM);
    #pragma unroll
    for (int l = 0; l < 8; ++l) {
        zr[l] = src[tid + l * 256];
        ((float4*)z)[tid + l * 256] = zr[l];
    }
    __syncthreads();

    {
        float s = 0.0f;
        #pragma unroll
        for (int l = 0; l < 8; ++l)
            s += zr[l].x + zr[l].y + zr[l].z + zr[l].w;
        s = blockReduceSum256(s, redS);
        if (tid == 0) {
            tau_sh = (s - 1.0f) / (float)NM;
            cprev_sh = NM;
            done_sh = 0;
        }
        __syncthreads();
    }

    for (int it = 0; it < 64; ++it) {
        float tau = tau_sh;
        float ls = 0.0f, lc = 0.0f;
        #pragma unroll
        for (int l = 0; l < 8; ++l) {
            if (zr[l].x > tau) { ls += zr[l].x; lc += 1.0f; }
            if (zr[l].y > tau) { ls += zr[l].y; lc += 1.0f; }
            if (zr[l].z > tau) { ls += zr[l].z; lc += 1.0f; }
            if (zr[l].w > tau) { ls += zr[l].w; lc += 1.0f; }
        }
        #pragma unroll
        for (int o = 16; o > 0; o >>= 1) {
            ls += __shfl_down_sync(0xffffffffu, ls, o);
            lc += __shfl_down_sync(0xffffffffu, lc, o);
        }
        int warp = tid >> 5, lane = tid & 31;
        if (lane == 0) { redS[warp] = ls; redC[warp] = lc; }
        __syncthreads();
        if (tid == 0) {
            float S = 0.0f, Cc = 0.0f;
            #pragma unroll
            for (int w = 0; w < 8; ++w) { S += redS[w]; Cc += redC[w]; }
            int c = (int)(Cc + 0.5f);
            if (c == cprev_sh || c <= 0) done_sh = 1;
            else { cprev_sh = c; tau_sh = (S - 1.0f) / (float)c; }
        }
        __syncthreads();
        if (done_sh) break;
    }
    const float tau = tau_sh;

    // deterministic compaction (thread owns its 8 float4s)
    int mycnt = 0;
    #pragma unroll
    for (int l = 0; l < 8; ++l) {
        if (zr[l].x > tau) mycnt++;
        if (zr[l].y > tau) mycnt++;
        if (zr[l].z > tau) mycnt++;
        if (zr[l].w > tau) mycnt++;
    }
    counts[tid] = mycnt;
    __syncthreads();
    if (tid == 0) {
        int run = 0;
        for (int t = 0; t < 256; ++t) { int c = counts[t]; counts[t] = run; run += c; }
        counts[256] = run;
    }
    __syncthreads();
    const int nnz = counts[256];
    if (nnz <= SPX_CAP) {
        int off = counts[tid];
        #pragma unroll
        for (int l = 0; l < 8; ++l) {
            int base = 4 * (tid + l * 256);
            if (zr[l].x > tau) idxs[off++] = (unsigned short)(base + 0);
            if (zr[l].y > tau) idxs[off++] = (unsigned short)(base + 1);
            if (zr[l].z > tau) idxs[off++] = (unsigned short)(base + 2);
            if (zr[l].w > tau) idxs[off++] = (unsigned short)(base + 3);
        }
    }
    __syncthreads();

    float4 acc = make_float4(0.f, 0.f, 0.f, 0.f);
    const float4* mem4 = (const float4*)mem;
    if (nnz <= SPX_CAP) {
        #pragma unroll 4
        for (int j = 0; j < nnz; ++j) {
            int m = idxs[j];
            float w = z[m] - tau;
            float4 v = mem4[(size_t)m * 256 + tid];
            acc.x += w * v.x; acc.y += w * v.y;
            acc.z += w * v.z; acc.w += w * v.w;
        }
    } else {
        for (int m = 0; m < NM; ++m) {
            float w = z[m] - tau;
            if (w > 0.0f) {
                float4 v = mem4[(size_t)m * 256 + tid];
                acc.x += w * v.x; acc.y += w * v.y;
                acc.z += w * v.z; acc.w += w * v.w;
            }
        }
    }
    half hx, lx, hy, ly, hz, lz, hw, lw;
    fp16_split(acc.x, hx, lx); fp16_split(acc.y, hy, ly);
    fp16_split(acc.z, hz, lz); fp16_split(acc.w, hw, lw);
    half* ph = g_cat_hi + (size_t)row * N2D + ND + tid * 4;
    half* pl = g_cat_lo + (size_t)row * N2D + ND + tid * 4;
    ph[0] = hx; ph[1] = hy; ph[2] = hz; ph[3] = hw;
    pl[0] = lx; pl[1] = ly; pl[2] = lz; pl[3] = lw;
}

// ---------------------------------------------------------------
// launch
// ---------------------------------------------------------------
extern "C" void kernel_launch(void* const* d_in, const int* in_sizes, int n_in,
                              void* d_out, int out_size) {
    const float* enc  = (const float*)d_in[0];  // [4096,1024]
    const float* mem  = (const float*)d_in[1];  // [8192,1024]
    const float* fc1w = (const float*)d_in[2];  // [4096,2048]
    const float* fc1b = (const float*)d_in[3];  // [4096]
    const float* fc2w = (const float*)d_in[4];  // [1000,4096]
    const float* fc2b = (const float*)d_in[5];  // [1000]
    float* out = (float*)d_out;                 // [4096,1000]

    void *p_xinv, *p_yinv, *p_sim, *p_cath, *p_catl, *p_memh,
         *p_hidh, *p_hidl, *p_w1h, *p_w2h;
    cudaGetSymbolAddress(&p_xinv, g_xinv);
    cudaGetSymbolAddress(&p_yinv, g_yinv);
    cudaGetSymbolAddress(&p_sim,  g_sim);
    cudaGetSymbolAddress(&p_cath, g_cat_hi);
    cudaGetSymbolAddress(&p_catl, g_cat_lo);
    cudaGetSymbolAddress(&p_memh, g_mem_h);
    cudaGetSymbolAddress(&p_hidh, g_hid_hi);
    cudaGetSymbolAddress(&p_hidl, g_hid_lo);
    cudaGetSymbolAddress(&p_w1h,  g_w1_h);
    cudaGetSymbolAddress(&p_w2h,  g_w2_h);

    cudaFuncSetAttribute(tc_gemm<1, 0>, cudaFuncAttributeMaxDynamicSharedMemorySize, GEMM_SMEM);
    cudaFuncSetAttribute(tc_gemm<2, 1>, cudaFuncAttributeMaxDynamicSharedMemorySize, GEMM_SMEM);
    cudaFuncSetAttribute(tc_gemm<2, 2>, cudaFuncAttributeMaxDynamicSharedMemorySize, GEMM_SMEM);

    // 1) norms + rounds/splits
    norm_enc_kernel<<<NB, 256>>>(enc);
    norm_mem_kernel<<<NM, 256>>>(mem);
    round_kernel<<<(int)(((size_t)NH * N2D / 4) / 256), 256>>>(fc1w, (half*)p_w1h);
    round_pad_w2_kernel<<<NOUTP, 256>>>(fc2w);

    // 2) sim = (enc @ mem^T) * xinv[row] * yinv[col]   (single-pass fp16)
    tc_gemm<1, 0><<<dim3(NM / 256, NB / 128), 256, GEMM_SMEM>>>(
        NM, ND, N2D, ND, NM,
        (const half*)p_cath, nullptr, (const half*)p_memh,
        (float*)p_sim, nullptr, nullptr,
        (const float*)p_xinv, (const float*)p_yinv, nullptr);

    // 3) sparsemax + sparse memory vector -> concat right half (fp16 split)
    sparsemax_mv_kernel<<<NB, 256>>>(mem);

    // 4) hidden = relu(concat @ fc1w^T + b) -> fp16 split stores (2-pass)
    tc_gemm<2, 1><<<dim3(NH / 256, NB / 128), 256, GEMM_SMEM>>>(
        NH, N2D, N2D, N2D, NH,
        (const half*)p_cath, (const half*)p_catl, (const half*)p_w1h,
        nullptr, (half*)p_hidh, (half*)p_hidl,
        nullptr, nullptr, fc1b);

    // 5) out = hidden @ fc2w^T + b  (padded N, store-guarded, 2-pass)
    tc_gemm<2, 2><<<dim3(NOUTP / 256, NB / 128), 256, GEMM_SMEM>>>(
        NOUTP, NH, NH, NH, NOUT,
        (const half*)p_hidh, (const half*)p_hidl, (const half*)p_w2h,
        out, nullptr, nullptr,
        nullptr, nullptr, fc2b);
}

// round 8
// speedup vs baseline: 4.2616x; 1.2845x over previous
#include <cuda_runtime.h>
#include <cuda_fp16.h>
#include <cstdint>

// Problem constants
#define NB   4096   // batch B
#define NM   8192   // memory rows M
#define ND   1024   // dim D
#define NOUT 1000   // output classes
#define NOUTP 1024  // padded output cols
#define NH   4096   // 4*D hidden
#define N2D  2048   // 2*D concat width

// -------- scratch (device globals; no allocation allowed) --------
__device__ float g_xinv[NB];
__device__ float g_yinv[NM];
__device__ float g_sim[(size_t)NB * NM];        // 128 MB
__device__ half  g_cat_h[(size_t)NB * N2D];     // 16 MB  [enc | mv] rounded
__device__ half  g_mem_h[(size_t)NM * ND];      // 16 MB
__device__ half  g_hid_h[(size_t)NB * NH];      // 32 MB
__device__ half  g_w1_h[(size_t)NH * N2D];      // 16 MB
__device__ half  g_w2_h[(size_t)NOUTP * NH];    // 8 MB (padded)

// ---------------------------------------------------------------
// helpers
// ---------------------------------------------------------------
__device__ __forceinline__ uint32_t cvta_smem(const void* p) {
    uint32_t a;
    asm("{ .reg .u64 t; cvta.to.shared.u64 t, %1; cvt.u32.u64 %0, t; }"
        : "=r"(a) : "l"(p));
    return a;
}

__device__ __forceinline__ void cp16(uint32_t dst, const void* src) {
    asm volatile("cp.async.cg.shared.global [%0], [%1], 16;" :: "r"(dst), "l"(src));
}

__device__ __forceinline__ void mma_fp16(float* d, const uint32_t* a, const uint32_t* b) {
    asm volatile(
        "mma.sync.aligned.m16n8k16.row.col.f32.f16.f16.f32 "
        "{%0,%1,%2,%3}, {%4,%5,%6,%7}, {%8,%9}, {%0,%1,%2,%3};"
        : "+f"(d[0]), "+f"(d[1]), "+f"(d[2]), "+f"(d[3])
        : "r"(a[0]), "r"(a[1]), "r"(a[2]), "r"(a[3]), "r"(b[0]), "r"(b[1]));
}

__device__ __forceinline__ void ldsm_x4(uint32_t* r, uint32_t addr) {
    asm volatile("ldmatrix.sync.aligned.m8n8.x4.shared.b16 {%0,%1,%2,%3}, [%4];"
                 : "=r"(r[0]), "=r"(r[1]), "=r"(r[2]), "=r"(r[3]) : "r"(addr));
}

__device__ __forceinline__ void ldsm_x2(uint32_t* r, uint32_t addr) {
    asm volatile("ldmatrix.sync.aligned.m8n8.x2.shared.b16 {%0,%1}, [%2];"
                 : "=r"(r[0]), "=r"(r[1]) : "r"(addr));
}

// ---------------------------------------------------------------
// block reduce (256 threads)
// ---------------------------------------------------------------
__device__ __forceinline__ float blockReduceSum256(float v, float* red) {
    __syncthreads();
    #pragma unroll
    for (int o = 16; o > 0; o >>= 1) v += __shfl_down_sync(0xffffffffu, v, o);
    int warp = threadIdx.x >> 5, lane = threadIdx.x & 31;
    if (lane == 0) red[warp] = v;
    __syncthreads();
    if (warp == 0) {
        v = (lane < 8) ? red[lane] : 0.0f;
        #pragma unroll
        for (int o = 4; o > 0; o >>= 1) v += __shfl_down_sync(0xffffffffu, v, o);
        if (lane == 0) red[0] = v;
    }
    __syncthreads();
    return red[0];
}

// ---------------------------------------------------------------
// encoder: 1/||x||, fp16 round of raw enc -> concat left half
// ---------------------------------------------------------------
__global__ __launch_bounds__(256) void norm_enc_kernel(const float* __restrict__ enc) {
    __shared__ float red[8];
    int row = blockIdx.x, tid = threadIdx.x;
    float4 v = ((const float4*)(enc + (size_t)row * ND))[tid];
    float s = v.x*v.x + v.y*v.y + v.z*v.z + v.w*v.w;
    s = blockReduceSum256(s, red);
    if (tid == 0) g_xinv[row] = rsqrtf(s + 1e-6f);
    half* ph = g_cat_h + (size_t)row * N2D + tid * 4;
    ph[0] = __float2half_rn(v.x); ph[1] = __float2half_rn(v.y);
    ph[2] = __float2half_rn(v.z); ph[3] = __float2half_rn(v.w);
}

// ---------------------------------------------------------------
// memory rows: 1/||y|| + fp16 round (B side)
// ---------------------------------------------------------------
__global__ __launch_bounds__(256) void norm_mem_kernel(const float* __restrict__ mem) {
    __shared__ float red[8];
    int row = blockIdx.x, tid = threadIdx.x;
    float4 v = ((const float4*)(mem + (size_t)row * ND))[tid];
    float s = v.x*v.x + v.y*v.y + v.z*v.z + v.w*v.w;
    s = blockReduceSum256(s, red);
    if (tid == 0) g_yinv[row] = rsqrtf(s + 1e-6f);
    half* ph = g_mem_h + (size_t)row * ND + tid * 4;
    ph[0] = __float2half_rn(v.x); ph[1] = __float2half_rn(v.y);
    ph[2] = __float2half_rn(v.z); ph[3] = __float2half_rn(v.w);
}

// ---------------------------------------------------------------
// fp32 -> fp16 round (weights)
// ---------------------------------------------------------------
__global__ __launch_bounds__(256) void round_kernel(
    const float* __restrict__ src, half* __restrict__ dst) {
    size_t i = (size_t)blockIdx.x * 256 + threadIdx.x;
    float4 v = ((const float4*)src)[i];
    half* p = dst + i * 4;
    p[0] = __float2half_rn(v.x); p[1] = __float2half_rn(v.y);
    p[2] = __float2half_rn(v.z); p[3] = __float2half_rn(v.w);
}

// fc2 weights: round + zero-pad rows [1000,1024)
__global__ __launch_bounds__(256) void round_pad_w2_kernel(const float* __restrict__ src) {
    int row = blockIdx.x, tid = threadIdx.x;  // 1024 rows x 4096 cols
    #pragma unroll
    for (int lq = 0; lq < 4; ++lq) {
        int idx = tid + 256 * lq;
        float4 v = make_float4(0.f, 0.f, 0.f, 0.f);
        if (row < NOUT) v = ((const float4*)(src + (size_t)row * NH))[idx];
        half* p = g_w2_h + (size_t)row * NH + idx * 4;
        p[0] = __float2half_rn(v.x); p[1] = __float2half_rn(v.y);
        p[2] = __float2half_rn(v.z); p[3] = __float2half_rn(v.w);
    }
}

// ---------------------------------------------------------------
// single-pass fp16 GEMM (mma.sync.m16n8k16 + ldmatrix):
//   C[M,N] = A[M,K] @ B[N,K]^T, fp32 accum
// 128x256 CTA tile, BK=64, 3-stage cp.async pipeline, ONE sync per chunk,
// 256 threads (8 warps 2x4, 64x64 warp tiles).
// EPI: 0 = sim (v * xinv[row] * yinv[col], fp32 store)
//      1 = fc1 (relu(v+bias) -> fp16 store)
//      2 = fc2 (v+bias, fp32 store guarded col<Nout, row stride Nout)
// ---------------------------------------------------------------
#define BKE     64                       // K elems per chunk
#define ROW_B   144                      // smem row stride bytes (128 + 16 pad)
#define A_T     (128 * ROW_B)            // 18432 bytes (A tile)
#define B_T     (256 * ROW_B)            // 36864 bytes (B tile)
#define STAGE_B (A_T + B_T)              // 55296
#define NSTAGE  3
#define GEMM_SMEM (NSTAGE * STAGE_B)     // 165888

template<int EPI>
__global__ __launch_bounds__(256, 1) void tc_gemm(
    int N, int K, int lda, int ldb, int Nout,
    const half* __restrict__ A0, const half* __restrict__ B0,
    float* __restrict__ C, half* __restrict__ Ch,
    const float* __restrict__ xinv, const float* __restrict__ yinv,
    const float* __restrict__ bias)
{
    extern __shared__ __align__(1024) char smraw[];
    const uint32_t smemU = cvta_smem(smraw);

    const int tid  = threadIdx.x;
    const int lane = tid & 31;
    const int wid  = tid >> 5;
    const int wm   = wid & 1;          // 0..1  (64-row block)
    const int wn   = wid >> 1;         // 0..3  (64-col block)
    const int row0 = blockIdx.y * 128;
    const int col0 = blockIdx.x * 256;

    const int nkc = K / BKE;

    // global->smem: A: 2 threads/row (64B each); B: 1 thread/row (128B)
    const int ldr = tid >> 1;
    const int ldh = tid & 1;
    const uint32_t aBase = smemU + ldr * ROW_B + ldh * 64;
    const uint32_t bBase = smemU + A_T + tid * ROW_B;

    auto do_load = [&](int ck, int s) {
        const uint32_t so = s * STAGE_B;
        const half* ga = A0 + (size_t)(row0 + ldr) * lda + ck * BKE + ldh * 32;
        #pragma unroll
        for (int i = 0; i < 4; ++i) cp16(aBase + so + i * 16, ga + i * 8);
        const half* gb = B0 + (size_t)(col0 + tid) * ldb + ck * BKE;
        #pragma unroll
        for (int i = 0; i < 8; ++i) cp16(bBase + so + i * 16, gb + i * 8);
    };

    float acc[4][8][4];
    #pragma unroll
    for (int mt = 0; mt < 4; ++mt)
        #pragma unroll
        for (int nt = 0; nt < 8; ++nt)
            #pragma unroll
            for (int c = 0; c < 4; ++c) acc[mt][nt][c] = 0.0f;

    do_load(0, 0);
    asm volatile("cp.async.commit_group;" ::: "memory");
    do_load(1, 1);
    asm volatile("cp.async.commit_group;" ::: "memory");

    // ldmatrix lane bases
    const uint32_t aFragBase = smemU + (wm * 64 + (lane & 15)) * ROW_B + (lane >> 4) * 16;
    const uint32_t bFragBase = smemU + A_T +
                               (wn * 64 + (lane & 7)) * ROW_B + ((lane >> 3) & 1) * 16;

    for (int it = 0; it < nkc; ++it) {
        if (it + 2 < nkc) {
            asm volatile("cp.async.wait_group 1;" ::: "memory");
        } else {
            asm volatile("cp.async.wait_group 0;" ::: "memory");
        }
        __syncthreads();   // orders: prior-iter reads done, this-iter stage visible
        if (it + 2 < nkc) {
            do_load(it + 2, (it + 2) % NSTAGE);
            asm volatile("cp.async.commit_group;" ::: "memory");
        }

        const uint32_t so = (it % NSTAGE) * STAGE_B;

        #pragma unroll
        for (int ks = 0; ks < 4; ++ks) {
            const uint32_t ko = ks * 32;
            uint32_t bfr[8][2];
            #pragma unroll
            for (int nt = 0; nt < 8; ++nt)
                ldsm_x2(bfr[nt], bFragBase + so + nt * (8 * ROW_B) + ko);

            uint32_t afr[4][4];
            #pragma unroll
            for (int mt = 0; mt < 4; ++mt)
                ldsm_x4(afr[mt], aFragBase + so + mt * (16 * ROW_B) + ko);
            #pragma unroll
            for (int mt = 0; mt < 4; ++mt)
                #pragma unroll
                for (int nt = 0; nt < 8; ++nt)
                    mma_fp16(acc[mt][nt], afr[mt], bfr[nt]);
        }
        // no trailing sync: top-of-loop sync covers the WAR hazard
    }

    // epilogue
    const int r = lane >> 2;
    const int q = lane & 3;
    #pragma unroll
    for (int mt = 0; mt < 4; ++mt) {
        const int gr0 = row0 + wm * 64 + mt * 16 + r;
        #pragma unroll
        for (int half_ = 0; half_ < 2; ++half_) {
            const int gr = gr0 + half_ * 8;
            float xr = 0.0f;
            if (EPI == 0) xr = xinv[gr];
            #pragma unroll
            for (int nt = 0; nt < 8; ++nt) {
                const int gc = col0 + wn * 64 + nt * 8 + q * 2;
                float v0 = acc[mt][nt][half_ * 2 + 0];
                float v1 = acc[mt][nt][half_ * 2 + 1];
                if (EPI == 0) {
                    float2 o = make_float2(v0 * xr * yinv[gc], v1 * xr * yinv[gc + 1]);
                    *(float2*)(C + (size_t)gr * N + gc) = o;
                } else if (EPI == 1) {
                    v0 = fmaxf(v0 + bias[gc], 0.0f);
                    v1 = fmaxf(v1 + bias[gc + 1], 0.0f);
                    __half2 hh;
                    hh.x = __float2half_rn(v0);
                    hh.y = __float2half_rn(v1);
                    *(__half2*)(Ch + (size_t)gr * N + gc) = hh;
                } else {
                    if (gc < Nout) {
                        float2 o = make_float2(v0 + bias[gc], v1 + bias[gc + 1]);
                        *(float2*)(C + (size_t)gr * Nout + gc) = o;
                    }
                }
            }
        }
    }
}

// ---------------------------------------------------------------
// Fused sparsemax (Michelot, sort-free, register-resident) + sparse
// memory-vector gather.  Writes fp16 rounded mv into concat right half.
// ---------------------------------------------------------------
#define SPX_CAP 4096
__global__ __launch_bounds__(256) void sparsemax_mv_kernel(const float* __restrict__ mem) {
    __shared__ float z[NM];                  // 32 KB
    __shared__ unsigned short idxs[SPX_CAP]; // 8 KB
    __shared__ float redS[8];
    __shared__ float redC[8];
    __shared__ int   counts[257];
    __shared__ float tau_sh;
    __shared__ int   cprev_sh;
    __shared__ int   done_sh;

    const int row = blockIdx.x;
    const int tid = threadIdx.x;

    // load sim row into regs + smem
    float4 zr[8];
    const float4* src = (const float4*)(g_sim + (size_t)row * NM);
    #pragma unroll
    for (int l = 0; l < 8; ++l) {
        zr[l] = src[tid + l * 256];
        ((float4*)z)[tid + l * 256] = zr[l];
    }
    __syncthreads();

    {
        float s = 0.0f;
        #pragma unroll
        for (int l = 0; l < 8; ++l)
            s += zr[l].x + zr[l].y + zr[l].z + zr[l].w;
        s = blockReduceSum256(s, redS);
        if (tid == 0) {
            tau_sh = (s - 1.0f) / (float)NM;
            cprev_sh = NM;
            done_sh = 0;
        }
        __syncthreads();
    }

    for (int it = 0; it < 64; ++it) {
        float tau = tau_sh;
        float ls = 0.0f, lc = 0.0f;
        #pragma unroll
        for (int l = 0; l < 8; ++l) {
            if (zr[l].x > tau) { ls += zr[l].x; lc += 1.0f; }
            if (zr[l].y > tau) { ls += zr[l].y; lc += 1.0f; }
            if (zr[l].z > tau) { ls += zr[l].z; lc += 1.0f; }
            if (zr[l].w > tau) { ls += zr[l].w; lc += 1.0f; }
        }
        #pragma unroll
        for (int o = 16; o > 0; o >>= 1) {
            ls += __shfl_down_sync(0xffffffffu, ls, o);
            lc += __shfl_down_sync(0xffffffffu, lc, o);
        }
        int warp = tid >> 5, lane = tid & 31;
        if (lane == 0) { redS[warp] = ls; redC[warp] = lc; }
        __syncthreads();
        if (tid == 0) {
            float S = 0.0f, Cc = 0.0f;
            #pragma unroll
            for (int w = 0; w < 8; ++w) { S += redS[w]; Cc += redC[w]; }
            int c = (int)(Cc + 0.5f);
            if (c == cprev_sh || c <= 0) done_sh = 1;
            else { cprev_sh = c; tau_sh = (S - 1.0f) / (float)c; }
        }
        __syncthreads();
        if (done_sh) break;
    }
    const float tau = tau_sh;

    // deterministic compaction (thread owns its 8 float4s)
    int mycnt = 0;
    #pragma unroll
    for (int l = 0; l < 8; ++l) {
        if (zr[l].x > tau) mycnt++;
        if (zr[l].y > tau) mycnt++;
        if (zr[l].z > tau) mycnt++;
        if (zr[l].w > tau) mycnt++;
    }
    counts[tid] = mycnt;
    __syncthreads();
    if (tid == 0) {
        int run = 0;
        for (int t = 0; t < 256; ++t) { int c = counts[t]; counts[t] = run; run += c; }
        counts[256] = run;
    }
    __syncthreads();
    const int nnz = counts[256];
    if (nnz <= SPX_CAP) {
        int off = counts[tid];
        #pragma unroll
        for (int l = 0; l < 8; ++l) {
            int base = 4 * (tid + l * 256);
            if (zr[l].x > tau) idxs[off++] = (unsigned short)(base + 0);
            if (zr[l].y > tau) idxs[off++] = (unsigned short)(base + 1);
            if (zr[l].z > tau) idxs[off++] = (unsigned short)(base + 2);
            if (zr[l].w > tau) idxs[off++] = (unsigned short)(base + 3);
        }
    }
    __syncthreads();

    float4 acc = make_float4(0.f, 0.f, 0.f, 0.f);
    const float4* mem4 = (const float4*)mem;
    if (nnz <= SPX_CAP) {
        #pragma unroll 4
        for (int j = 0; j < nnz; ++j) {
            int m = idxs[j];
            float w = z[m] - tau;
            float4 v = mem4[(size_t)m * 256 + tid];
            acc.x += w * v.x; acc.y += w * v.y;
            acc.z += w * v.z; acc.w += w * v.w;
        }
    } else {
        for (int m = 0; m < NM; ++m) {
            float w = z[m] - tau;
            if (w > 0.0f) {
                float4 v = mem4[(size_t)m * 256 + tid];
                acc.x += w * v.x; acc.y += w * v.y;
                acc.z += w * v.z; acc.w += w * v.w;
            }
        }
    }
    half* ph = g_cat_h + (size_t)row * N2D + ND + tid * 4;
    ph[0] = __float2half_rn(acc.x); ph[1] = __float2half_rn(acc.y);
    ph[2] = __float2half_rn(acc.z); ph[3] = __float2half_rn(acc.w);
}

// ---------------------------------------------------------------
// launch
// ---------------------------------------------------------------
extern "C" void kernel_launch(void* const* d_in, const int* in_sizes, int n_in,
                              void* d_out, int out_size) {
    const float* enc  = (const float*)d_in[0];  // [4096,1024]
    const float* mem  = (const float*)d_in[1];  // [8192,1024]
    const float* fc1w = (const float*)d_in[2];  // [4096,2048]
    const float* fc1b = (const float*)d_in[3];  // [4096]
    const float* fc2w = (const float*)d_in[4];  // [1000,4096]
    const float* fc2b = (const float*)d_in[5];  // [1000]
    float* out = (float*)d_out;                 // [4096,1000]

    void *p_xinv, *p_yinv, *p_sim, *p_cath, *p_memh, *p_hidh, *p_w1h, *p_w2h;
    cudaGetSymbolAddress(&p_xinv, g_xinv);
    cudaGetSymbolAddress(&p_yinv, g_yinv);
    cudaGetSymbolAddress(&p_sim,  g_sim);
    cudaGetSymbolAddress(&p_cath, g_cat_h);
    cudaGetSymbolAddress(&p_memh, g_mem_h);
    cudaGetSymbolAddress(&p_hidh, g_hid_h);
    cudaGetSymbolAddress(&p_w1h,  g_w1_h);
    cudaGetSymbolAddress(&p_w2h,  g_w2_h);

    cudaFuncSetAttribute(tc_gemm<0>, cudaFuncAttributeMaxDynamicSharedMemorySize, GEMM_SMEM);
    cudaFuncSetAttribute(tc_gemm<1>, cudaFuncAttributeMaxDynamicSharedMemorySize, GEMM_SMEM);
    cudaFuncSetAttribute(tc_gemm<2>, cudaFuncAttributeMaxDynamicSharedMemorySize, GEMM_SMEM);

    // 1) norms + rounds
    norm_enc_kernel<<<NB, 256>>>(enc);
    norm_mem_kernel<<<NM, 256>>>(mem);
    round_kernel<<<(int)(((size_t)NH * N2D / 4) / 256), 256>>>(fc1w, (half*)p_w1h);
    round_pad_w2_kernel<<<NOUTP, 256>>>(fc2w);

    // 2) sim = (enc @ mem^T) * xinv[row] * yinv[col]
    tc_gemm<0><<<dim3(NM / 256, NB / 128), 256, GEMM_SMEM>>>(
        NM, ND, N2D, ND, NM,
        (const half*)p_cath, (const half*)p_memh,
        (float*)p_sim, nullptr,
        (const float*)p_xinv, (const float*)p_yinv, nullptr);

    // 3) sparsemax + sparse memory vector -> concat right half
    sparsemax_mv_kernel<<<NB, 256>>>(mem);

    // 4) hidden = relu(concat @ fc1w^T + b) -> fp16 store
    tc_gemm<1><<<dim3(NH / 256, NB / 128), 256, GEMM_SMEM>>>(
        NH, N2D, N2D, N2D, NH,
        (const half*)p_cath, (const half*)p_w1h,
        nullptr, (half*)p_hidh,
        nullptr, nullptr, fc1b);

    // 5) out = hidden @ fc2w^T + b  (padded N, store-guarded)
    tc_gemm<2><<<dim3(NOUTP / 256, NB / 128), 256, GEMM_SMEM>>>(
        NOUTP, NH, NH, NH, NOUT,
        (const half*)p_hidh, (const half*)p_w2h,
        out, nullptr,
        nullptr, nullptr, fc2b);
}

// round 10
// speedup vs baseline: 4.4151x; 1.0360x over previous
#include <cuda_runtime.h>
#include <cuda_fp16.h>
#include <cstdint>

// Problem constants
#define NB   4096   // batch B
#define NM   8192   // memory rows M
#define ND   1024   // dim D
#define NOUT 1000   // output classes
#define NOUTP 1024  // padded output cols
#define NH   4096   // 4*D hidden
#define N2D  2048   // 2*D concat width

// -------- scratch (device globals; no allocation allowed) --------
__device__ float g_xinv[NB];
__device__ float g_yinv[NM];
__device__ half  g_sim[(size_t)NB * NM];        // 64 MB (fp16 sims)
__device__ half  g_cat_h[(size_t)NB * N2D];     // 16 MB  [enc | mv] rounded
__device__ half  g_mem_h[(size_t)NM * ND];      // 16 MB
__device__ half  g_hid_h[(size_t)NB * NH];      // 32 MB
__device__ half  g_w1_h[(size_t)NH * N2D];      // 16 MB
__device__ half  g_w2_h[(size_t)NOUTP * NH];    // 8 MB (padded)

// ---------------------------------------------------------------
// helpers
// ---------------------------------------------------------------
__device__ __forceinline__ uint32_t cvta_smem(const void* p) {
    uint32_t a;
    asm("{ .reg .u64 t; cvta.to.shared.u64 t, %1; cvt.u32.u64 %0, t; }"
        : "=r"(a) : "l"(p));
    return a;
}

__device__ __forceinline__ void cp16(uint32_t dst, const void* src) {
    asm volatile("cp.async.cg.shared.global [%0], [%1], 16;" :: "r"(dst), "l"(src));
}

__device__ __forceinline__ void mma_fp16(float* d, const uint32_t* a, const uint32_t* b) {
    asm volatile(
        "mma.sync.aligned.m16n8k16.row.col.f32.f16.f16.f32 "
        "{%0,%1,%2,%3}, {%4,%5,%6,%7}, {%8,%9}, {%0,%1,%2,%3};"
        : "+f"(d[0]), "+f"(d[1]), "+f"(d[2]), "+f"(d[3])
        : "r"(a[0]), "r"(a[1]), "r"(a[2]), "r"(a[3]), "r"(b[0]), "r"(b[1]));
}

__device__ __forceinline__ void ldsm_x4(uint32_t* r, uint32_t addr) {
    asm volatile("ldmatrix.sync.aligned.m8n8.x4.shared.b16 {%0,%1,%2,%3}, [%4];"
                 : "=r"(r[0]), "=r"(r[1]), "=r"(r[2]), "=r"(r[3]) : "r"(addr));
}

__device__ __forceinline__ void ldsm_x2(uint32_t* r, uint32_t addr) {
    asm volatile("ldmatrix.sync.aligned.m8n8.x2.shared.b16 {%0,%1}, [%2];"
                 : "=r"(r[0]), "=r"(r[1]) : "r"(addr));
}

// ---------------------------------------------------------------
// block reduce (256 threads)
// ---------------------------------------------------------------
__device__ __forceinline__ float blockReduceSum256(float v, float* red) {
    __syncthreads();
    #pragma unroll
    for (int o = 16; o > 0; o >>= 1) v += __shfl_down_sync(0xffffffffu, v, o);
    int warp = threadIdx.x >> 5, lane = threadIdx.x & 31;
    if (lane == 0) red[warp] = v;
    __syncthreads();
    if (warp == 0) {
        v = (lane < 8) ? red[lane] : 0.0f;
        #pragma unroll
        for (int o = 4; o > 0; o >>= 1) v += __shfl_down_sync(0xffffffffu, v, o);
        if (lane == 0) red[0] = v;
    }
    __syncthreads();
    return red[0];
}

// ---------------------------------------------------------------
// encoder: 1/||x||, fp16 round of raw enc -> concat left half
// ---------------------------------------------------------------
__global__ __launch_bounds__(256) void norm_enc_kernel(const float* __restrict__ enc) {
    __shared__ float red[8];
    int row = blockIdx.x, tid = threadIdx.x;
    float4 v = ((const float4*)(enc + (size_t)row * ND))[tid];
    float s = v.x*v.x + v.y*v.y + v.z*v.z + v.w*v.w;
    s = blockReduceSum256(s, red);
    if (tid == 0) g_xinv[row] = rsqrtf(s + 1e-6f);
    half* ph = g_cat_h + (size_t)row * N2D + tid * 4;
    ph[0] = __float2half_rn(v.x); ph[1] = __float2half_rn(v.y);
    ph[2] = __float2half_rn(v.z); ph[3] = __float2half_rn(v.w);
}

// ---------------------------------------------------------------
// memory rows: 1/||y|| + fp16 round (B side)
// ---------------------------------------------------------------
__global__ __launch_bounds__(256) void norm_mem_kernel(const float* __restrict__ mem) {
    __shared__ float red[8];
    int row = blockIdx.x, tid = threadIdx.x;
    float4 v = ((const float4*)(mem + (size_t)row * ND))[tid];
    float s = v.x*v.x + v.y*v.y + v.z*v.z + v.w*v.w;
    s = blockReduceSum256(s, red);
    if (tid == 0) g_yinv[row] = rsqrtf(s + 1e-6f);
    half* ph = g_mem_h + (size_t)row * ND + tid * 4;
    ph[0] = __float2half_rn(v.x); ph[1] = __float2half_rn(v.y);
    ph[2] = __float2half_rn(v.z); ph[3] = __float2half_rn(v.w);
}

// ---------------------------------------------------------------
// fp32 -> fp16 round (weights)
// ---------------------------------------------------------------
__global__ __launch_bounds__(256) void round_kernel(
    const float* __restrict__ src, half* __restrict__ dst) {
    size_t i = (size_t)blockIdx.x * 256 + threadIdx.x;
    float4 v = ((const float4*)src)[i];
    half* p = dst + i * 4;
    p[0] = __float2half_rn(v.x); p[1] = __float2half_rn(v.y);
    p[2] = __float2half_rn(v.z); p[3] = __float2half_rn(v.w);
}

// fc2 weights: round + zero-pad rows [1000,1024)
__global__ __launch_bounds__(256) void round_pad_w2_kernel(const float* __restrict__ src) {
    int row = blockIdx.x, tid = threadIdx.x;  // 1024 rows x 4096 cols
    #pragma unroll
    for (int lq = 0; lq < 4; ++lq) {
        int idx = tid + 256 * lq;
        float4 v = make_float4(0.f, 0.f, 0.f, 0.f);
        if (row < NOUT) v = ((const float4*)(src + (size_t)row * NH))[idx];
        half* p = g_w2_h + (size_t)row * NH + idx * 4;
        p[0] = __float2half_rn(v.x); p[1] = __float2half_rn(v.y);
        p[2] = __float2half_rn(v.z); p[3] = __float2half_rn(v.w);
    }
}

// ---------------------------------------------------------------
// single-pass fp16 GEMM (mma.sync.m16n8k16 + ldmatrix):
//   C[M,N] = A[M,K] @ B[N,K]^T, fp32 accum
// 128x256 CTA tile, BK=64, 3-stage cp.async pipeline, one sync per chunk,
// 256 threads (8 warps 2x4, 64x64 warp tiles).
// EPI: 0 = sim (v * xinv[row] * yinv[col], fp16 store)
//      1 = fc1 (relu(v+bias) -> fp16 store)
//      2 = fc2 (v+bias, fp32 store guarded col<Nout, row stride Nout)
// ---------------------------------------------------------------
#define BKE     64                       // K elems per chunk
#define ROW_B   144                      // smem row stride bytes (128 + 16 pad)
#define A_T     (128 * ROW_B)            // 18432 bytes (A tile)
#define B_T     (256 * ROW_B)            // 36864 bytes (B tile)
#define STAGE_B (A_T + B_T)              // 55296
#define NSTAGE  3
#define GEMM_SMEM (NSTAGE * STAGE_B)     // 165888

template<int EPI>
__global__ __launch_bounds__(256, 1) void tc_gemm(
    int N, int K, int lda, int ldb, int Nout,
    const half* __restrict__ A0, const half* __restrict__ B0,
    float* __restrict__ C, half* __restrict__ Ch,
    const float* __restrict__ xinv, const float* __restrict__ yinv,
    const float* __restrict__ bias)
{
    extern __shared__ __align__(1024) char smraw[];
    const uint32_t smemU = cvta_smem(smraw);

    const int tid  = threadIdx.x;
    const int lane = tid & 31;
    const int wid  = tid >> 5;
    const int wm   = wid & 1;          // 0..1  (64-row block)
    const int wn   = wid >> 1;         // 0..3  (64-col block)
    const int row0 = blockIdx.y * 128;
    const int col0 = blockIdx.x * 256;

    const int nkc = K / BKE;

    // global->smem: A: 2 threads/row (64B each); B: 1 thread/row (128B)
    const int ldr = tid >> 1;
    const int ldh = tid & 1;
    const uint32_t aBase = smemU + ldr * ROW_B + ldh * 64;
    const uint32_t bBase = smemU + A_T + tid * ROW_B;

    auto do_load = [&](int ck, int s) {
        const uint32_t so = s * STAGE_B;
        const half* ga = A0 + (size_t)(row0 + ldr) * lda + ck * BKE + ldh * 32;
        #pragma unroll
        for (int i = 0; i < 4; ++i) cp16(aBase + so + i * 16, ga + i * 8);
        const half* gb = B0 + (size_t)(col0 + tid) * ldb + ck * BKE;
        #pragma unroll
        for (int i = 0; i < 8; ++i) cp16(bBase + so + i * 16, gb + i * 8);
    };

    float acc[4][8][4];
    #pragma unroll
    for (int mt = 0; mt < 4; ++mt)
        #pragma unroll
        for (int nt = 0; nt < 8; ++nt)
            #pragma unroll
            for (int c = 0; c < 4; ++c) acc[mt][nt][c] = 0.0f;

    do_load(0, 0);
    asm volatile("cp.async.commit_group;" ::: "memory");
    do_load(1, 1);
    asm volatile("cp.async.commit_group;" ::: "memory");

    // ldmatrix lane bases
    const uint32_t aFragBase = smemU + (wm * 64 + (lane & 15)) * ROW_B + (lane >> 4) * 16;
    const uint32_t bFragBase = smemU + A_T +
                               (wn * 64 + (lane & 7)) * ROW_B + ((lane >> 3) & 1) * 16;

    for (int it = 0; it < nkc; ++it) {
        if (it + 2 < nkc) {
            asm volatile("cp.async.wait_group 1;" ::: "memory");
        } else {
            asm volatile("cp.async.wait_group 0;" ::: "memory");
        }
        __syncthreads();   // orders: prior-iter reads done, this-iter stage visible
        if (it + 2 < nkc) {
            do_load(it + 2, (it + 2) % NSTAGE);
            asm volatile("cp.async.commit_group;" ::: "memory");
        }

        const uint32_t so = (it % NSTAGE) * STAGE_B;

        #pragma unroll
        for (int ks = 0; ks < 4; ++ks) {
            const uint32_t ko = ks * 32;
            uint32_t bfr[8][2];
            #pragma unroll
            for (int nt = 0; nt < 8; ++nt)
                ldsm_x2(bfr[nt], bFragBase + so + nt * (8 * ROW_B) + ko);

            uint32_t afr[4][4];
            #pragma unroll
            for (int mt = 0; mt < 4; ++mt)
                ldsm_x4(afr[mt], aFragBase + so + mt * (16 * ROW_B) + ko);
            #pragma unroll
            for (int mt = 0; mt < 4; ++mt)
                #pragma unroll
                for (int nt = 0; nt < 8; ++nt)
                    mma_fp16(acc[mt][nt], afr[mt], bfr[nt]);
        }
    }

    // epilogue
    const int r = lane >> 2;
    const int q = lane & 3;
    #pragma unroll
    for (int mt = 0; mt < 4; ++mt) {
        const int gr0 = row0 + wm * 64 + mt * 16 + r;
        #pragma unroll
        for (int half_ = 0; half_ < 2; ++half_) {
            const int gr = gr0 + half_ * 8;
            float xr = 0.0f;
            if (EPI == 0) xr = xinv[gr];
            #pragma unroll
            for (int nt = 0; nt < 8; ++nt) {
                const int gc = col0 + wn * 64 + nt * 8 + q * 2;
                float v0 = acc[mt][nt][half_ * 2 + 0];
                float v1 = acc[mt][nt][half_ * 2 + 1];
                if (EPI == 0) {
                    __half2 hh;
                    hh.x = __float2half_rn(v0 * xr * yinv[gc]);
                    hh.y = __float2half_rn(v1 * xr * yinv[gc + 1]);
                    *(__half2*)(Ch + (size_t)gr * N + gc) = hh;
                } else if (EPI == 1) {
                    v0 = fmaxf(v0 + bias[gc], 0.0f);
                    v1 = fmaxf(v1 + bias[gc + 1], 0.0f);
                    __half2 hh;
                    hh.x = __float2half_rn(v0);
                    hh.y = __float2half_rn(v1);
                    *(__half2*)(Ch + (size_t)gr * N + gc) = hh;
                } else {
                    if (gc < Nout) {
                        float2 o = make_float2(v0 + bias[gc], v1 + bias[gc + 1]);
                        *(float2*)(C + (size_t)gr * Nout + gc) = o;
                    }
                }
            }
        }
    }
}

// ---------------------------------------------------------------
// Fused sparsemax (Michelot, sort-free, register-resident) + sparse
// memory-vector gather.  z input is fp16 (g_sim); math in fp32 regs.
// smem ~25.5 KB -> 8 CTAs/SM.  Parallel prefix scan for compaction.
// ---------------------------------------------------------------
#define SPX_CAP 4096
__global__ __launch_bounds__(256) void sparsemax_mv_kernel(const float* __restrict__ mem) {
    __shared__ __align__(16) half zh[NM];    // 16 KB (half copy for gather)
    __shared__ unsigned short idxs[SPX_CAP]; // 8 KB
    __shared__ float redS[8];
    __shared__ float redC[8];
    __shared__ int   wtot[8];
    __shared__ int   wpre[8];
    __shared__ float tau_sh;
    __shared__ int   cprev_sh;
    __shared__ int   done_sh;

    const int row = blockIdx.x;
    const int tid = threadIdx.x;
    const int warp = tid >> 5, lane = tid & 31;

    // load sim row (8192 half = 1024 x 16B): 4 uint4 per thread
    float zr[32];
    {
        const uint4* src = (const uint4*)(g_sim + (size_t)row * NM);
        #pragma unroll
        for (int l = 0; l < 4; ++l) {
            uint4 raw = src[tid + l * 256];
            ((uint4*)zh)[tid + l * 256] = raw;
            const __half2* hp = (const __half2*)&raw;
            #pragma unroll
            for (int k = 0; k < 4; ++k) {
                float2 f = __half22float2(hp[k]);
                zr[l * 8 + 2 * k]     = f.x;
                zr[l * 8 + 2 * k + 1] = f.y;
            }
        }
    }
    __syncthreads();

    {
        float s = 0.0f;
        #pragma unroll
        for (int i = 0; i < 32; ++i) s += zr[i];
        s = blockReduceSum256(s, redS);
        if (tid == 0) {
            tau_sh = (s - 1.0f) / (float)NM;
            cprev_sh = NM;
            done_sh = 0;
        }
        __syncthreads();
    }

    for (int it = 0; it < 64; ++it) {
        float tau = tau_sh;
        float ls = 0.0f, lc = 0.0f;
        #pragma unroll
        for (int i = 0; i < 32; ++i)
            if (zr[i] > tau) { ls += zr[i]; lc += 1.0f; }
        #pragma unroll
        for (int o = 16; o > 0; o >>= 1) {
            ls += __shfl_down_sync(0xffffffffu, ls, o);
            lc += __shfl_down_sync(0xffffffffu, lc, o);
        }
        if (lane == 0) { redS[warp] = ls; redC[warp] = lc; }
        __syncthreads();
        if (tid == 0) {
            float S = 0.0f, Cc = 0.0f;
            #pragma unroll
            for (int w = 0; w < 8; ++w) { S += redS[w]; Cc += redC[w]; }
            int c = (int)(Cc + 0.5f);
            if (c == cprev_sh || c <= 0) done_sh = 1;
            else { cprev_sh = c; tau_sh = (S - 1.0f) / (float)c; }
        }
        __syncthreads();
        if (done_sh) break;
    }
    const float tau = tau_sh;

    // count per thread
    int mycnt = 0;
    #pragma unroll
    for (int i = 0; i < 32; ++i)
        if (zr[i] > tau) mycnt++;

    // parallel prefix scan (warp inclusive scan + warp-leader scan)
    int csum = mycnt;
    #pragma unroll
    for (int o = 1; o < 32; o <<= 1) {
        int n = __shfl_up_sync(0xffffffffu, csum, o);
        if (lane >= o) csum += n;
    }
    if (lane == 31) wtot[warp] = csum;
    __syncthreads();
    if (warp == 0 && lane < 8) {
        int t = wtot[lane];
        #pragma unroll
        for (int o = 1; o < 8; o <<= 1) {
            int n = __shfl_up_sync(0x000000ffu, t, o);
            if (lane >= o) t += n;
        }
        wpre[lane] = t;
    }
    __syncthreads();
    const int nnz = wpre[7];
    if (nnz <= SPX_CAP) {
        int off = (warp ? wpre[warp - 1] : 0) + csum - mycnt;
        #pragma unroll
        for (int l = 0; l < 4; ++l) {
            int base = 8 * (tid + l * 256);
            #pragma unroll
            for (int j = 0; j < 8; ++j)
                if (zr[l * 8 + j] > tau) idxs[off++] = (unsigned short)(base + j);
        }
    }
    __syncthreads();

    float4 acc = make_float4(0.f, 0.f, 0.f, 0.f);
    const float4* mem4 = (const float4*)mem;
    if (nnz <= SPX_CAP) {
        #pragma unroll 4
        for (int j = 0; j < nnz; ++j) {
            int m = idxs[j];
            float w = __half2float(zh[m]) - tau;
            float4 v = mem4[(size_t)m * 256 + tid];
            acc.x += w * v.x; acc.y += w * v.y;
            acc.z += w * v.z; acc.w += w * v.w;
        }
    } else {
        for (int m = 0; m < NM; ++m) {
            float w = __half2float(zh[m]) - tau;
            if (w > 0.0f) {
                float4 v = mem4[(size_t)m * 256 + tid];
                acc.x += w * v.x; acc.y += w * v.y;
                acc.z += w * v.z; acc.w += w * v.w;
            }
        }
    }
    half* ph = g_cat_h + (size_t)row * N2D + ND + tid * 4;
    ph[0] = __float2half_rn(acc.x); ph[1] = __float2half_rn(acc.y);
    ph[2] = __float2half_rn(acc.z); ph[3] = __float2half_rn(acc.w);
}

// ---------------------------------------------------------------
// launch
// ---------------------------------------------------------------
extern "C" void kernel_launch(void* const* d_in, const int* in_sizes, int n_in,
                              void* d_out, int out_size) {
    const float* enc  = (const float*)d_in[0];  // [4096,1024]
    const float* mem  = (const float*)d_in[1];  // [8192,1024]
    const float* fc1w = (const float*)d_in[2];  // [4096,2048]
    const float* fc1b = (const float*)d_in[3];  // [4096]
    const float* fc2w = (const float*)d_in[4];  // [1000,4096]
    const float* fc2b = (const float*)d_in[5];  // [1000]
    float* out = (float*)d_out;                 // [4096,1000]

    void *p_xinv, *p_yinv, *p_sim, *p_cath, *p_memh, *p_hidh, *p_w1h, *p_w2h;
    cudaGetSymbolAddress(&p_xinv, g_xinv);
    cudaGetSymbolAddress(&p_yinv, g_yinv);
    cudaGetSymbolAddress(&p_sim,  g_sim);
    cudaGetSymbolAddress(&p_cath, g_cat_h);
    cudaGetSymbolAddress(&p_memh, g_mem_h);
    cudaGetSymbolAddress(&p_hidh, g_hid_h);
    cudaGetSymbolAddress(&p_w1h,  g_w1_h);
    cudaGetSymbolAddress(&p_w2h,  g_w2_h);

    cudaFuncSetAttribute(tc_gemm<0>, cudaFuncAttributeMaxDynamicSharedMemorySize, GEMM_SMEM);
    cudaFuncSetAttribute(tc_gemm<1>, cudaFuncAttributeMaxDynamicSharedMemorySize, GEMM_SMEM);
    cudaFuncSetAttribute(tc_gemm<2>, cudaFuncAttributeMaxDynamicSharedMemorySize, GEMM_SMEM);

    // 1) norms + rounds
    norm_enc_kernel<<<NB, 256>>>(enc);
    norm_mem_kernel<<<NM, 256>>>(mem);
    round_kernel<<<(int)(((size_t)NH * N2D / 4) / 256), 256>>>(fc1w, (half*)p_w1h);
    round_pad_w2_kernel<<<NOUTP, 256>>>(fc2w);

    // 2) sim = (enc @ mem^T) * xinv[row] * yinv[col]  -> fp16
    tc_gemm<0><<<dim3(NM / 256, NB / 128), 256, GEMM_SMEM>>>(
        NM, ND, N2D, ND, NM,
        (const half*)p_cath, (const half*)p_memh,
        nullptr, (half*)p_sim,
        (const float*)p_xinv, (const float*)p_yinv, nullptr);

    // 3) sparsemax + sparse memory vector -> concat right half
    sparsemax_mv_kernel<<<NB, 256>>>(mem);

    // 4) hidden = relu(concat @ fc1w^T + b) -> fp16 store
    tc_gemm<1><<<dim3(NH / 256, NB / 128), 256, GEMM_SMEM>>>(
        NH, N2D, N2D, N2D, NH,
        (const half*)p_cath, (const half*)p_w1h,
        nullptr, (half*)p_hidh,
        nullptr, nullptr, fc1b);

    // 5) out = hidden @ fc2w^T + b  (padded N, store-guarded)
    tc_gemm<2><<<dim3(NOUTP / 256, NB / 128), 256, GEMM_SMEM>>>(
        NOUTP, NH, NH, NH, NOUT,
        (const half*)p_hidh, (const half*)p_w2h,
        out, nullptr,
        nullptr, nullptr, fc2b);
}

// round 11
// speedup vs baseline: 6.1197x; 1.3861x over previous
#include <cuda_runtime.h>
#include <cuda_fp16.h>
#include <cstdint>

// Problem constants
#define NB   4096   // batch B
#define NM   8192   // memory rows M
#define ND   1024   // dim D
#define NOUT 1000   // output classes
#define NOUTP 1024  // padded output cols
#define NH   4096   // 4*D hidden
#define N2D  2048   // 2*D concat width

// -------- scratch (device globals; no allocation allowed) --------
__device__ float g_xinv[NB];
__device__ float g_yinv[NM];
__device__ half  g_sim[(size_t)NB * NM];        // 64 MB (fp16 sims)
__device__ half  g_cat_h[(size_t)NB * N2D];     // 16 MB  [enc | mv] rounded
__device__ half  g_mem_h[(size_t)NM * ND];      // 16 MB
__device__ half  g_hid_h[(size_t)NB * NH];      // 32 MB
__device__ half  g_w1_h[(size_t)NH * N2D];      // 16 MB
__device__ half  g_w2_h[(size_t)NOUTP * NH];    // 8 MB (padded)

// ---------------------------------------------------------------
// helpers
// ---------------------------------------------------------------
__device__ __forceinline__ uint32_t cvta_smem(const void* p) {
    uint32_t a;
    asm("{ .reg .u64 t; cvta.to.shared.u64 t, %1; cvt.u32.u64 %0, t; }"
        : "=r"(a) : "l"(p));
    return a;
}

__device__ __forceinline__ void cp16(uint32_t dst, const void* src) {
    asm volatile("cp.async.cg.shared.global [%0], [%1], 16;" :: "r"(dst), "l"(src));
}

__device__ __forceinline__ void mma_fp16(float* d, const uint32_t* a, const uint32_t* b) {
    asm volatile(
        "mma.sync.aligned.m16n8k16.row.col.f32.f16.f16.f32 "
        "{%0,%1,%2,%3}, {%4,%5,%6,%7}, {%8,%9}, {%0,%1,%2,%3};"
        : "+f"(d[0]), "+f"(d[1]), "+f"(d[2]), "+f"(d[3])
        : "r"(a[0]), "r"(a[1]), "r"(a[2]), "r"(a[3]), "r"(b[0]), "r"(b[1]));
}

__device__ __forceinline__ void ldsm_x4(uint32_t* r, uint32_t addr) {
    asm volatile("ldmatrix.sync.aligned.m8n8.x4.shared.b16 {%0,%1,%2,%3}, [%4];"
                 : "=r"(r[0]), "=r"(r[1]), "=r"(r[2]), "=r"(r[3]) : "r"(addr));
}

// ---------------------------------------------------------------
// block reduce (256 threads)
// ---------------------------------------------------------------
__device__ __forceinline__ float blockReduceSum256(float v, float* red) {
    __syncthreads();
    #pragma unroll
    for (int o = 16; o > 0; o >>= 1) v += __shfl_down_sync(0xffffffffu, v, o);
    int warp = threadIdx.x >> 5, lane = threadIdx.x & 31;
    if (lane == 0) red[warp] = v;
    __syncthreads();
    if (warp == 0) {
        v = (lane < 8) ? red[lane] : 0.0f;
        #pragma unroll
        for (int o = 4; o > 0; o >>= 1) v += __shfl_down_sync(0xffffffffu, v, o);
        if (lane == 0) red[0] = v;
    }
    __syncthreads();
    return red[0];
}

// ---------------------------------------------------------------
// encoder: 1/||x||, fp16 round of raw enc -> concat left half
// ---------------------------------------------------------------
__global__ __launch_bounds__(256) void norm_enc_kernel(const float* __restrict__ enc) {
    __shared__ float red[8];
    int row = blockIdx.x, tid = threadIdx.x;
    float4 v = ((const float4*)(enc + (size_t)row * ND))[tid];
    float s = v.x*v.x + v.y*v.y + v.z*v.z + v.w*v.w;
    s = blockReduceSum256(s, red);
    if (tid == 0) g_xinv[row] = rsqrtf(s + 1e-6f);
    half* ph = g_cat_h + (size_t)row * N2D + tid * 4;
    ph[0] = __float2half_rn(v.x); ph[1] = __float2half_rn(v.y);
    ph[2] = __float2half_rn(v.z); ph[3] = __float2half_rn(v.w);
}

// ---------------------------------------------------------------
// memory rows: 1/||y|| + fp16 round (B side)
// ---------------------------------------------------------------
__global__ __launch_bounds__(256) void norm_mem_kernel(const float* __restrict__ mem) {
    __shared__ float red[8];
    int row = blockIdx.x, tid = threadIdx.x;
    float4 v = ((const float4*)(mem + (size_t)row * ND))[tid];
    float s = v.x*v.x + v.y*v.y + v.z*v.z + v.w*v.w;
    s = blockReduceSum256(s, red);
    if (tid == 0) g_yinv[row] = rsqrtf(s + 1e-6f);
    half* ph = g_mem_h + (size_t)row * ND + tid * 4;
    ph[0] = __float2half_rn(v.x); ph[1] = __float2half_rn(v.y);
    ph[2] = __float2half_rn(v.z); ph[3] = __float2half_rn(v.w);
}

// ---------------------------------------------------------------
// fp32 -> fp16 round (weights)
// ---------------------------------------------------------------
__global__ __launch_bounds__(256) void round_kernel(
    const float* __restrict__ src, half* __restrict__ dst) {
    size_t i = (size_t)blockIdx.x * 256 + threadIdx.x;
    float4 v = ((const float4*)src)[i];
    half* p = dst + i * 4;
    p[0] = __float2half_rn(v.x); p[1] = __float2half_rn(v.y);
    p[2] = __float2half_rn(v.z); p[3] = __float2half_rn(v.w);
}

// fc2 weights: round + zero-pad rows [1000,1024)
__global__ __launch_bounds__(256) void round_pad_w2_kernel(const float* __restrict__ src) {
    int row = blockIdx.x, tid = threadIdx.x;  // 1024 rows x 4096 cols
    #pragma unroll
    for (int lq = 0; lq < 4; ++lq) {
        int idx = tid + 256 * lq;
        float4 v = make_float4(0.f, 0.f, 0.f, 0.f);
        if (row < NOUT) v = ((const float4*)(src + (size_t)row * NH))[idx];
        half* p = g_w2_h + (size_t)row * NH + idx * 4;
        p[0] = __float2half_rn(v.x); p[1] = __float2half_rn(v.y);
        p[2] = __float2half_rn(v.z); p[3] = __float2half_rn(v.w);
    }
}

// ---------------------------------------------------------------
// single-pass fp16 GEMM (mma.sync.m16n8k16 + ldmatrix):
//   C[M,N] = A[M,K] @ B[N,K]^T, fp32 accum
// 128x256 CTA tile, BK=64, 3-stage cp.async pipeline, one sync per chunk,
// 256 threads (8 warps 2x4, 64x64 warp tiles).
// COALESCED tile loads: 8 lanes cover one row's 128B -> 4 full lines per
// warp cp.async instruction.
// EPI: 0 = sim (v * xinv[row] * yinv[col], fp16 store)
//      1 = fc1 (relu(v+bias) -> fp16 store)
//      2 = fc2 (v+bias, fp32 store guarded col<Nout, row stride Nout)
// ---------------------------------------------------------------
#define BKE     64                       // K elems per chunk
#define ROW_B   144                      // smem row stride bytes (128 + 16 pad)
#define A_T     (128 * ROW_B)            // 18432 bytes (A tile)
#define B_T     (256 * ROW_B)            // 36864 bytes (B tile)
#define STAGE_B (A_T + B_T)              // 55296
#define NSTAGE  3
#define GEMM_SMEM (NSTAGE * STAGE_B)     // 165888

template<int EPI>
__global__ __launch_bounds__(256, 1) void tc_gemm(
    int N, int K, int lda, int ldb, int Nout,
    const half* __restrict__ A0, const half* __restrict__ B0,
    float* __restrict__ C, half* __restrict__ Ch,
    const float* __restrict__ xinv, const float* __restrict__ yinv,
    const float* __restrict__ bias)
{
    extern __shared__ __align__(1024) char smraw[];
    const uint32_t smemU = cvta_smem(smraw);

    const int tid  = threadIdx.x;
    const int lane = tid & 31;
    const int wid  = tid >> 5;
    const int wm   = wid & 1;          // 0..1  (64-row block)
    const int wn   = wid >> 1;         // 0..3  (64-col block)
    const int row0 = blockIdx.y * 128;
    const int col0 = blockIdx.x * 256;

    const int nkc = K / BKE;

    // COALESCED global->smem mapping: 8 lanes per row (16B each);
    // a warp instruction covers 4 consecutive rows x 128B = 4 full lines.
    const int wr  = tid >> 3;          // 0..31 row group
    const int lc8 = tid & 7;           // 16B slot within row
    const uint32_t aBase = smemU + wr * ROW_B + lc8 * 16;
    const uint32_t bBase = smemU + A_T + wr * ROW_B + lc8 * 16;

    auto do_load = [&](int ck, int s) {
        const uint32_t so = s * STAGE_B;
        const half* ga = A0 + (size_t)(row0 + wr) * lda + ck * BKE + lc8 * 8;
        #pragma unroll
        for (int i = 0; i < 4; ++i)
            cp16(aBase + so + i * (32 * ROW_B), ga + (size_t)(32 * i) * lda);
        const half* gb = B0 + (size_t)(col0 + wr) * ldb + ck * BKE + lc8 * 8;
        #pragma unroll
        for (int i = 0; i < 8; ++i)
            cp16(bBase + so + i * (32 * ROW_B), gb + (size_t)(32 * i) * ldb);
    };

    float acc[4][8][4];
    #pragma unroll
    for (int mt = 0; mt < 4; ++mt)
        #pragma unroll
        for (int nt = 0; nt < 8; ++nt)
            #pragma unroll
            for (int c = 0; c < 4; ++c) acc[mt][nt][c] = 0.0f;

    do_load(0, 0);
    asm volatile("cp.async.commit_group;" ::: "memory");
    do_load(1, 1);
    asm volatile("cp.async.commit_group;" ::: "memory");

    // ldmatrix lane bases
    // A x4: lanes 0-15 rows, lanes>>4 selects k-halves (16B)
    const uint32_t aFragBase = smemU + (wm * 64 + (lane & 15)) * ROW_B + (lane >> 4) * 16;
    // B x4: covers TWO 8-col n-tiles per instruction:
    //   lanes 0-7  : rows nt0+0..7,  k0-7
    //   lanes 8-15 : rows nt0+0..7,  k8-15
    //   lanes 16-23: rows nt0+8..15, k0-7
    //   lanes 24-31: rows nt0+8..15, k8-15
    const uint32_t bFragBase = smemU + A_T +
        (wn * 64 + (lane & 7) + ((lane >> 4) & 1) * 8) * ROW_B + ((lane >> 3) & 1) * 16;

    for (int it = 0; it < nkc; ++it) {
        if (it + 2 < nkc) {
            asm volatile("cp.async.wait_group 1;" ::: "memory");
        } else {
            asm volatile("cp.async.wait_group 0;" ::: "memory");
        }
        __syncthreads();   // orders: prior-iter reads done, this-iter stage visible
        if (it + 2 < nkc) {
            do_load(it + 2, (it + 2) % NSTAGE);
            asm volatile("cp.async.commit_group;" ::: "memory");
        }

        const uint32_t so = (it % NSTAGE) * STAGE_B;

        #pragma unroll
        for (int ks = 0; ks < 4; ++ks) {
            const uint32_t ko = ks * 32;
            uint32_t bfr[16];   // [nt*2 + j]
            #pragma unroll
            for (int p = 0; p < 4; ++p)
                ldsm_x4(&bfr[4 * p], bFragBase + so + p * (16 * ROW_B) + ko);

            uint32_t afr[4][4];
            #pragma unroll
            for (int mt = 0; mt < 4; ++mt)
                ldsm_x4(afr[mt], aFragBase + so + mt * (16 * ROW_B) + ko);
            #pragma unroll
            for (int mt = 0; mt < 4; ++mt)
                #pragma unroll
                for (int nt = 0; nt < 8; ++nt)
                    mma_fp16(acc[mt][nt], afr[mt], &bfr[nt * 2]);
        }
    }

    // epilogue
    const int r = lane >> 2;
    const int q = lane & 3;
    #pragma unroll
    for (int mt = 0; mt < 4; ++mt) {
        const int gr0 = row0 + wm * 64 + mt * 16 + r;
        #pragma unroll
        for (int half_ = 0; half_ < 2; ++half_) {
            const int gr = gr0 + half_ * 8;
            float xr = 0.0f;
            if (EPI == 0) xr = xinv[gr];
            #pragma unroll
            for (int nt = 0; nt < 8; ++nt) {
                const int gc = col0 + wn * 64 + nt * 8 + q * 2;
                float v0 = acc[mt][nt][half_ * 2 + 0];
                float v1 = acc[mt][nt][half_ * 2 + 1];
                if (EPI == 0) {
                    __half2 hh;
                    hh.x = __float2half_rn(v0 * xr * yinv[gc]);
                    hh.y = __float2half_rn(v1 * xr * yinv[gc + 1]);
                    *(__half2*)(Ch + (size_t)gr * N + gc) = hh;
                } else if (EPI == 1) {
                    v0 = fmaxf(v0 + bias[gc], 0.0f);
                    v1 = fmaxf(v1 + bias[gc + 1], 0.0f);
                    __half2 hh;
                    hh.x = __float2half_rn(v0);
                    hh.y = __float2half_rn(v1);
                    *(__half2*)(Ch + (size_t)gr * N + gc) = hh;
                } else {
                    if (gc < Nout) {
                        float2 o = make_float2(v0 + bias[gc], v1 + bias[gc + 1]);
                        *(float2*)(C + (size_t)gr * Nout + gc) = o;
                    }
                }
            }
        }
    }
}

// ---------------------------------------------------------------
// Fused sparsemax (Michelot, sort-free, register-resident) + sparse
// memory-vector gather.  z input is fp16 (g_sim); math in fp32 regs.
// smem ~25.5 KB -> 8 CTAs/SM.  Parallel prefix scan for compaction.
// ---------------------------------------------------------------
#define SPX_CAP 4096
__global__ __launch_bounds__(256) void sparsemax_mv_kernel(const float* __restrict__ mem) {
    __shared__ __align__(16) half zh[NM];    // 16 KB (half copy for gather)
    __shared__ unsigned short idxs[SPX_CAP]; // 8 KB
    __shared__ float redS[8];
    __shared__ float redC[8];
    __shared__ int   wtot[8];
    __shared__ int   wpre[8];
    __shared__ float tau_sh;
    __shared__ int   cprev_sh;
    __shared__ int   done_sh;

    const int row = blockIdx.x;
    const int tid = threadIdx.x;
    const int warp = tid >> 5, lane = tid & 31;

    // load sim row (8192 half = 1024 x 16B): 4 uint4 per thread
    float zr[32];
    {
        const uint4* src = (const uint4*)(g_sim + (size_t)row * NM);
        #pragma unroll
        for (int l = 0; l < 4; ++l) {
            uint4 raw = src[tid + l * 256];
            ((uint4*)zh)[tid + l * 256] = raw;
            const __half2* hp = (const __half2*)&raw;
            #pragma unroll
            for (int k = 0; k < 4; ++k) {
                float2 f = __half22float2(hp[k]);
                zr[l * 8 + 2 * k]     = f.x;
                zr[l * 8 + 2 * k + 1] = f.y;
            }
        }
    }
    __syncthreads();

    {
        float s = 0.0f;
        #pragma unroll
        for (int i = 0; i < 32; ++i) s += zr[i];
        s = blockReduceSum256(s, redS);
        if (tid == 0) {
            tau_sh = (s - 1.0f) / (float)NM;
            cprev_sh = NM;
            done_sh = 0;
        }
        __syncthreads();
    }

    for (int it = 0; it < 64; ++it) {
        float tau = tau_sh;
        float ls = 0.0f, lc = 0.0f;
        #pragma unroll
        for (int i = 0; i < 32; ++i)
            if (zr[i] > tau) { ls += zr[i]; lc += 1.0f; }
        #pragma unroll
        for (int o = 16; o > 0; o >>= 1) {
            ls += __shfl_down_sync(0xffffffffu, ls, o);
            lc += __shfl_down_sync(0xffffffffu, lc, o);
        }
        if (lane == 0) { redS[warp] = ls; redC[warp] = lc; }
        __syncthreads();
        if (tid == 0) {
            float S = 0.0f, Cc = 0.0f;
            #pragma unroll
            for (int w = 0; w < 8; ++w) { S += redS[w]; Cc += redC[w]; }
            int c = (int)(Cc + 0.5f);
            if (c == cprev_sh || c <= 0) done_sh = 1;
            else { cprev_sh = c; tau_sh = (S - 1.0f) / (float)c; }
        }
        __syncthreads();
        if (done_sh) break;
    }
    const float tau = tau_sh;

    // count per thread
    int mycnt = 0;
    #pragma unroll
    for (int i = 0; i < 32; ++i)
        if (zr[i] > tau) mycnt++;

    // parallel prefix scan (warp inclusive scan + warp-leader scan)
    int csum = mycnt;
    #pragma unroll
    for (int o = 1; o < 32; o <<= 1) {
        int n = __shfl_up_sync(0xffffffffu, csum, o);
        if (lane >= o) csum += n;
    }
    if (lane == 31) wtot[warp] = csum;
    __syncthreads();
    if (warp == 0 && lane < 8) {
        int t = wtot[lane];
        #pragma unroll
        for (int o = 1; o < 8; o <<= 1) {
            int n = __shfl_up_sync(0x000000ffu, t, o);
            if (lane >= o) t += n;
        }
        wpre[lane] = t;
    }
    __syncthreads();
    const int nnz = wpre[7];
    if (nnz <= SPX_CAP) {
        int off = (warp ? wpre[warp - 1] : 0) + csum - mycnt;
        #pragma unroll
        for (int l = 0; l < 4; ++l) {
            int base = 8 * (tid + l * 256);
            #pragma unroll
            for (int j = 0; j < 8; ++j)
                if (zr[l * 8 + j] > tau) idxs[off++] = (unsigned short)(base + j);
        }
    }
    __syncthreads();

    float4 acc = make_float4(0.f, 0.f, 0.f, 0.f);
    const float4* mem4 = (const float4*)mem;
    if (nnz <= SPX_CAP) {
        #pragma unroll 4
        for (int j = 0; j < nnz; ++j) {
            int m = idxs[j];
            float w = __half2float(zh[m]) - tau;
            float4 v = mem4[(size_t)m * 256 + tid];
            acc.x += w * v.x; acc.y += w * v.y;
            acc.z += w * v.z; acc.w += w * v.w;
        }
    } else {
        for (int m = 0; m < NM; ++m) {
            float w = __half2float(zh[m]) - tau;
            if (w > 0.0f) {
                float4 v = mem4[(size_t)m * 256 + tid];
                acc.x += w * v.x; acc.y += w * v.y;
                acc.z += w * v.z; acc.w += w * v.w;
            }
        }
    }
    half* ph = g_cat_h + (size_t)row * N2D + ND + tid * 4;
    ph[0] = __float2half_rn(acc.x); ph[1] = __float2half_rn(acc.y);
    ph[2] = __float2half_rn(acc.z); ph[3] = __float2half_rn(acc.w);
}

// ---------------------------------------------------------------
// launch
// ---------------------------------------------------------------
extern "C" void kernel_launch(void* const* d_in, const int* in_sizes, int n_in,
                              void* d_out, int out_size) {
    const float* enc  = (const float*)d_in[0];  // [4096,1024]
    const float* mem  = (const float*)d_in[1];  // [8192,1024]
    const float* fc1w = (const float*)d_in[2];  // [4096,2048]
    const float* fc1b = (const float*)d_in[3];  // [4096]
    const float* fc2w = (const float*)d_in[4];  // [1000,4096]
    const float* fc2b = (const float*)d_in[5];  // [1000]
    float* out = (float*)d_out;                 // [4096,1000]

    void *p_xinv, *p_yinv, *p_sim, *p_cath, *p_memh, *p_hidh, *p_w1h, *p_w2h;
    cudaGetSymbolAddress(&p_xinv, g_xinv);
    cudaGetSymbolAddress(&p_yinv, g_yinv);
    cudaGetSymbolAddress(&p_sim,  g_sim);
    cudaGetSymbolAddress(&p_cath, g_cat_h);
    cudaGetSymbolAddress(&p_memh, g_mem_h);
    cudaGetSymbolAddress(&p_hidh, g_hid_h);
    cudaGetSymbolAddress(&p_w1h,  g_w1_h);
    cudaGetSymbolAddress(&p_w2h,  g_w2_h);

    cudaFuncSetAttribute(tc_gemm<0>, cudaFuncAttributeMaxDynamicSharedMemorySize, GEMM_SMEM);
    cudaFuncSetAttribute(tc_gemm<1>, cudaFuncAttributeMaxDynamicSharedMemorySize, GEMM_SMEM);
    cudaFuncSetAttribute(tc_gemm<2>, cudaFuncAttributeMaxDynamicSharedMemorySize, GEMM_SMEM);

    // 1) norms + rounds
    norm_enc_kernel<<<NB, 256>>>(enc);
    norm_mem_kernel<<<NM, 256>>>(mem);
    round_kernel<<<(int)(((size_t)NH * N2D / 4) / 256), 256>>>(fc1w, (half*)p_w1h);
    round_pad_w2_kernel<<<NOUTP, 256>>>(fc2w);

    // 2) sim = (enc @ mem^T) * xinv[row] * yinv[col]  -> fp16
    tc_gemm<0><<<dim3(NM / 256, NB / 128), 256, GEMM_SMEM>>>(
        NM, ND, N2D, ND, NM,
        (const half*)p_cath, (const half*)p_memh,
        nullptr, (half*)p_sim,
        (const float*)p_xinv, (const float*)p_yinv, nullptr);

    // 3) sparsemax + sparse memory vector -> concat right half
    sparsemax_mv_kernel<<<NB, 256>>>(mem);

    // 4) hidden = relu(concat @ fc1w^T + b) -> fp16 store
    tc_gemm<1><<<dim3(NH / 256, NB / 128), 256, GEMM_SMEM>>>(
        NH, N2D, N2D, N2D, NH,
        (const half*)p_cath, (const half*)p_w1h,
        nullptr, (half*)p_hidh,
        nullptr, nullptr, fc1b);

    // 5) out = hidden @ fc2w^T + b  (padded N, store-guarded)
    tc_gemm<2><<<dim3(NOUTP / 256, NB / 128), 256, GEMM_SMEM>>>(
        NOUTP, NH, NH, NH, NOUT,
        (const half*)p_hidh, (const half*)p_w2h,
        out, nullptr,
        nullptr, nullptr, fc2b);
}

// round 12
// speedup vs baseline: 6.1683x; 1.0079x over previous
#include <cuda_runtime.h>
#include <cuda_fp16.h>
#include <cstdint>

// Problem constants
#define NB   4096   // batch B
#define NM   8192   // memory rows M
#define ND   1024   // dim D
#define NOUT 1000   // output classes
#define NOUTP 1024  // padded output cols
#define NH   4096   // 4*D hidden
#define N2D  2048   // 2*D concat width

// -------- scratch (device globals; no allocation allowed) --------
__device__ float g_xinv[NB];
__device__ float g_yinv[NM];
__device__ half  g_sim[(size_t)NB * NM];        // 64 MB (fp16 sims)
__device__ half  g_cat_h[(size_t)NB * N2D];     // 16 MB  [enc | mv] rounded
__device__ half  g_mem_h[(size_t)NM * ND];      // 16 MB
__device__ half  g_hid_h[(size_t)NB * NH];      // 32 MB
__device__ half  g_w1_h[(size_t)NH * N2D];      // 16 MB
__device__ half  g_w2_h[(size_t)NOUTP * NH];    // 8 MB (padded)

// ---------------------------------------------------------------
// helpers
// ---------------------------------------------------------------
__device__ __forceinline__ uint32_t cvta_smem(const void* p) {
    uint32_t a;
    asm("{ .reg .u64 t; cvta.to.shared.u64 t, %1; cvt.u32.u64 %0, t; }"
        : "=r"(a) : "l"(p));
    return a;
}

__device__ __forceinline__ void cp16(uint32_t dst, const void* src) {
    asm volatile("cp.async.cg.shared.global [%0], [%1], 16;" :: "r"(dst), "l"(src));
}

__device__ __forceinline__ void mma_fp16(float* d, const uint32_t* a, const uint32_t* b) {
    asm volatile(
        "mma.sync.aligned.m16n8k16.row.col.f32.f16.f16.f32 "
        "{%0,%1,%2,%3}, {%4,%5,%6,%7}, {%8,%9}, {%0,%1,%2,%3};"
        : "+f"(d[0]), "+f"(d[1]), "+f"(d[2]), "+f"(d[3])
        : "r"(a[0]), "r"(a[1]), "r"(a[2]), "r"(a[3]), "r"(b[0]), "r"(b[1]));
}

__device__ __forceinline__ void ldsm_x4(uint32_t* r, uint32_t addr) {
    asm volatile("ldmatrix.sync.aligned.m8n8.x4.shared.b16 {%0,%1,%2,%3}, [%4];"
                 : "=r"(r[0]), "=r"(r[1]), "=r"(r[2]), "=r"(r[3]) : "r"(addr));
}

// ---------------------------------------------------------------
// block reduce (256 threads)
// ---------------------------------------------------------------
__device__ __forceinline__ float blockReduceSum256(float v, float* red) {
    __syncthreads();
    #pragma unroll
    for (int o = 16; o > 0; o >>= 1) v += __shfl_down_sync(0xffffffffu, v, o);
    int warp = threadIdx.x >> 5, lane = threadIdx.x & 31;
    if (lane == 0) red[warp] = v;
    __syncthreads();
    if (warp == 0) {
        v = (lane < 8) ? red[lane] : 0.0f;
        #pragma unroll
        for (int o = 4; o > 0; o >>= 1) v += __shfl_down_sync(0xffffffffu, v, o);
        if (lane == 0) red[0] = v;
    }
    __syncthreads();
    return red[0];
}

// ---------------------------------------------------------------
// encoder: 1/||x||, fp16 round of raw enc -> concat left half
// ---------------------------------------------------------------
__global__ __launch_bounds__(256) void norm_enc_kernel(const float* __restrict__ enc) {
    __shared__ float red[8];
    int row = blockIdx.x, tid = threadIdx.x;
    float4 v = ((const float4*)(enc + (size_t)row * ND))[tid];
    float s = v.x*v.x + v.y*v.y + v.z*v.z + v.w*v.w;
    s = blockReduceSum256(s, red);
    if (tid == 0) g_xinv[row] = rsqrtf(s + 1e-6f);
    half* ph = g_cat_h + (size_t)row * N2D + tid * 4;
    ph[0] = __float2half_rn(v.x); ph[1] = __float2half_rn(v.y);
    ph[2] = __float2half_rn(v.z); ph[3] = __float2half_rn(v.w);
}

// ---------------------------------------------------------------
// memory rows: 1/||y|| + fp16 round (B side)
// ---------------------------------------------------------------
__global__ __launch_bounds__(256) void norm_mem_kernel(const float* __restrict__ mem) {
    __shared__ float red[8];
    int row = blockIdx.x, tid = threadIdx.x;
    float4 v = ((const float4*)(mem + (size_t)row * ND))[tid];
    float s = v.x*v.x + v.y*v.y + v.z*v.z + v.w*v.w;
    s = blockReduceSum256(s, red);
    if (tid == 0) g_yinv[row] = rsqrtf(s + 1e-6f);
    half* ph = g_mem_h + (size_t)row * ND + tid * 4;
    ph[0] = __float2half_rn(v.x); ph[1] = __float2half_rn(v.y);
    ph[2] = __float2half_rn(v.z); ph[3] = __float2half_rn(v.w);
}

// ---------------------------------------------------------------
// fp32 -> fp16 round (weights)
// ---------------------------------------------------------------
__global__ __launch_bounds__(256) void round_kernel(
    const float* __restrict__ src, half* __restrict__ dst) {
    size_t i = (size_t)blockIdx.x * 256 + threadIdx.x;
    float4 v = ((const float4*)src)[i];
    half* p = dst + i * 4;
    p[0] = __float2half_rn(v.x); p[1] = __float2half_rn(v.y);
    p[2] = __float2half_rn(v.z); p[3] = __float2half_rn(v.w);
}

// fc2 weights: round + zero-pad rows [1000,1024)
__global__ __launch_bounds__(256) void round_pad_w2_kernel(const float* __restrict__ src) {
    int row = blockIdx.x, tid = threadIdx.x;  // 1024 rows x 4096 cols
    #pragma unroll
    for (int lq = 0; lq < 4; ++lq) {
        int idx = tid + 256 * lq;
        float4 v = make_float4(0.f, 0.f, 0.f, 0.f);
        if (row < NOUT) v = ((const float4*)(src + (size_t)row * NH))[idx];
        half* p = g_w2_h + (size_t)row * NH + idx * 4;
        p[0] = __float2half_rn(v.x); p[1] = __float2half_rn(v.y);
        p[2] = __float2half_rn(v.z); p[3] = __float2half_rn(v.w);
    }
}

// ---------------------------------------------------------------
// single-pass fp16 GEMM (mma.sync.m16n8k16 + ldmatrix):
//   C[M,N] = A[M,K] @ B[N,K]^T, fp32 accum
// 128x256 CTA tile, BK=64, 3-stage cp.async pipeline, one sync per chunk,
// 256 threads (8 warps 2x4, 64x64 warp tiles).
// Coalesced tile loads (8 lanes cover one 128B row).
// EPI 0/1 use a smem-staged, fully-coalesced fp16 store path.
// EPI: 0 = sim (v * xinv[row] * yinv[col], fp16 store)
//      1 = fc1 (relu(v+bias) -> fp16 store)
//      2 = fc2 (v+bias, fp32 store guarded col<Nout, row stride Nout)
// ---------------------------------------------------------------
#define BKE     64                       // K elems per chunk
#define ROW_B   144                      // smem row stride bytes (128 + 16 pad)
#define A_T     (128 * ROW_B)            // 18432 bytes (A tile)
#define B_T     (256 * ROW_B)            // 36864 bytes (B tile)
#define STAGE_B (A_T + B_T)              // 55296
#define NSTAGE  3
#define GEMM_SMEM (NSTAGE * STAGE_B)     // 165888
#define OUT_SROW 264                     // staging stride in halves (528 B)

template<int EPI>
__global__ __launch_bounds__(256, 1) void tc_gemm(
    int N, int K, int lda, int ldb, int Nout,
    const half* __restrict__ A0, const half* __restrict__ B0,
    float* __restrict__ C, half* __restrict__ Ch,
    const float* __restrict__ xinv, const float* __restrict__ yinv,
    const float* __restrict__ bias)
{
    extern __shared__ __align__(1024) char smraw[];
    const uint32_t smemU = cvta_smem(smraw);

    const int tid  = threadIdx.x;
    const int lane = tid & 31;
    const int wid  = tid >> 5;
    const int wm   = wid & 1;          // 0..1  (64-row block)
    const int wn   = wid >> 1;         // 0..3  (64-col block)
    const int row0 = blockIdx.y * 128;
    const int col0 = blockIdx.x * 256;

    const int nkc = K / BKE;

    // Coalesced global->smem mapping: 8 lanes per row (16B each).
    const int wr  = tid >> 3;          // 0..31 row group
    const int lc8 = tid & 7;           // 16B slot within row
    const uint32_t aBase = smemU + wr * ROW_B + lc8 * 16;
    const uint32_t bBase = smemU + A_T + wr * ROW_B + lc8 * 16;

    auto do_load = [&](int ck, int s) {
        const uint32_t so = s * STAGE_B;
        const half* ga = A0 + (size_t)(row0 + wr) * lda + ck * BKE + lc8 * 8;
        #pragma unroll
        for (int i = 0; i < 4; ++i)
            cp16(aBase + so + i * (32 * ROW_B), ga + (size_t)(32 * i) * lda);
        const half* gb = B0 + (size_t)(col0 + wr) * ldb + ck * BKE + lc8 * 8;
        #pragma unroll
        for (int i = 0; i < 8; ++i)
            cp16(bBase + so + i * (32 * ROW_B), gb + (size_t)(32 * i) * ldb);
    };

    float acc[4][8][4];
    #pragma unroll
    for (int mt = 0; mt < 4; ++mt)
        #pragma unroll
        for (int nt = 0; nt < 8; ++nt)
            #pragma unroll
            for (int c = 0; c < 4; ++c) acc[mt][nt][c] = 0.0f;

    do_load(0, 0);
    asm volatile("cp.async.commit_group;" ::: "memory");
    do_load(1, 1);
    asm volatile("cp.async.commit_group;" ::: "memory");

    // ldmatrix lane bases
    const uint32_t aFragBase = smemU + (wm * 64 + (lane & 15)) * ROW_B + (lane >> 4) * 16;
    const uint32_t bFragBase = smemU + A_T +
        (wn * 64 + (lane & 7) + ((lane >> 4) & 1) * 8) * ROW_B + ((lane >> 3) & 1) * 16;

    for (int it = 0; it < nkc; ++it) {
        if (it + 2 < nkc) {
            asm volatile("cp.async.wait_group 1;" ::: "memory");
        } else {
            asm volatile("cp.async.wait_group 0;" ::: "memory");
        }
        __syncthreads();
        if (it + 2 < nkc) {
            do_load(it + 2, (it + 2) % NSTAGE);
            asm volatile("cp.async.commit_group;" ::: "memory");
        }

        const uint32_t so = (it % NSTAGE) * STAGE_B;

        #pragma unroll
        for (int ks = 0; ks < 4; ++ks) {
            const uint32_t ko = ks * 32;
            uint32_t bfr[16];
            #pragma unroll
            for (int p = 0; p < 4; ++p)
                ldsm_x4(&bfr[4 * p], bFragBase + so + p * (16 * ROW_B) + ko);

            uint32_t afr[4][4];
            #pragma unroll
            for (int mt = 0; mt < 4; ++mt)
                ldsm_x4(afr[mt], aFragBase + so + mt * (16 * ROW_B) + ko);
            #pragma unroll
            for (int mt = 0; mt < 4; ++mt)
                #pragma unroll
                for (int nt = 0; nt < 8; ++nt)
                    mma_fp16(acc[mt][nt], afr[mt], &bfr[nt * 2]);
        }
    }

    // epilogue
    const int r = lane >> 2;
    const int q = lane & 3;

    if (EPI == 2) {
        // fp32 direct path (small output, edge-guarded)
        #pragma unroll
        for (int mt = 0; mt < 4; ++mt) {
            const int gr0 = row0 + wm * 64 + mt * 16 + r;
            #pragma unroll
            for (int half_ = 0; half_ < 2; ++half_) {
                const int gr = gr0 + half_ * 8;
                #pragma unroll
                for (int nt = 0; nt < 8; ++nt) {
                    const int gc = col0 + wn * 64 + nt * 8 + q * 2;
                    if (gc < Nout) {
                        float2 o = make_float2(acc[mt][nt][half_ * 2 + 0] + bias[gc],
                                               acc[mt][nt][half_ * 2 + 1] + bias[gc + 1]);
                        *(float2*)(C + (size_t)gr * Nout + gc) = o;
                    }
                }
            }
        }
    } else {
        // fp16 staged path: acc -> smem (conflict-free) -> coalesced uint4 stores
        __syncthreads();   // all warps done reading stage smem
        half* stg = (half*)smraw;
        #pragma unroll
        for (int mt = 0; mt < 4; ++mt) {
            const int lr0 = wm * 64 + mt * 16 + r;
            #pragma unroll
            for (int half_ = 0; half_ < 2; ++half_) {
                const int lr = lr0 + half_ * 8;
                float xr = 0.0f;
                if (EPI == 0) xr = xinv[row0 + lr];
                #pragma unroll
                for (int nt = 0; nt < 8; ++nt) {
                    const int lcL = wn * 64 + nt * 8 + q * 2;
                    float v0 = acc[mt][nt][half_ * 2 + 0];
                    float v1 = acc[mt][nt][half_ * 2 + 1];
                    __half2 hh;
                    if (EPI == 0) {
                        const int gc = col0 + lcL;
                        hh.x = __float2half_rn(v0 * xr * yinv[gc]);
                        hh.y = __float2half_rn(v1 * xr * yinv[gc + 1]);
                    } else {
                        const int gc = col0 + lcL;
                        hh.x = __float2half_rn(fmaxf(v0 + bias[gc], 0.0f));
                        hh.y = __float2half_rn(fmaxf(v1 + bias[gc + 1], 0.0f));
                    }
                    *(__half2*)(stg + lr * OUT_SROW + lcL) = hh;
                }
            }
        }
        __syncthreads();
        // coalesced: 128 rows x 32 uint4 (512B/row); warp covers one row segment
        #pragma unroll
        for (int i = 0; i < 16; ++i) {
            const int idx  = tid + i * 256;
            const int rrow = idx >> 5;
            const int slot = idx & 31;
            uint4 v = *(const uint4*)(stg + rrow * OUT_SROW + slot * 8);
            *(uint4*)(Ch + (size_t)(row0 + rrow) * N + col0 + slot * 8) = v;
        }
    }
}

// ---------------------------------------------------------------
// Fused sparsemax (Michelot, sort-free, register-resident) + sparse
// memory-vector gather.  z input is fp16 (g_sim); math in fp32 regs.
// ---------------------------------------------------------------
#define SPX_CAP 4096
__global__ __launch_bounds__(256) void sparsemax_mv_kernel(const float* __restrict__ mem) {
    __shared__ __align__(16) half zh[NM];    // 16 KB
    __shared__ unsigned short idxs[SPX_CAP]; // 8 KB
    __shared__ float redS[8];
    __shared__ float redC[8];
    __shared__ int   wtot[8];
    __shared__ int   wpre[8];
    __shared__ float tau_sh;
    __shared__ int   cprev_sh;
    __shared__ int   done_sh;

    const int row = blockIdx.x;
    const int tid = threadIdx.x;
    const int warp = tid >> 5, lane = tid & 31;

    float zr[32];
    {
        const uint4* src = (const uint4*)(g_sim + (size_t)row * NM);
        #pragma unroll
        for (int l = 0; l < 4; ++l) {
            uint4 raw = src[tid + l * 256];
            ((uint4*)zh)[tid + l * 256] = raw;
            const __half2* hp = (const __half2*)&raw;
            #pragma unroll
            for (int k = 0; k < 4; ++k) {
                float2 f = __half22float2(hp[k]);
                zr[l * 8 + 2 * k]     = f.x;
                zr[l * 8 + 2 * k + 1] = f.y;
            }
        }
    }
    __syncthreads();

    {
        float s = 0.0f;
        #pragma unroll
        for (int i = 0; i < 32; ++i) s += zr[i];
        s = blockReduceSum256(s, redS);
        if (tid == 0) {
            tau_sh = (s - 1.0f) / (float)NM;
            cprev_sh = NM;
            done_sh = 0;
        }
        __syncthreads();
    }

    for (int it = 0; it < 64; ++it) {
        float tau = tau_sh;
        float ls = 0.0f, lc = 0.0f;
        #pragma unroll
        for (int i = 0; i < 32; ++i)
            if (zr[i] > tau) { ls += zr[i]; lc += 1.0f; }
        #pragma unroll
        for (int o = 16; o > 0; o >>= 1) {
            ls += __shfl_down_sync(0xffffffffu, ls, o);
            lc += __shfl_down_sync(0xffffffffu, lc, o);
        }
        if (lane == 0) { redS[warp] = ls; redC[warp] = lc; }
        __syncthreads();
        if (tid == 0) {
            float S = 0.0f, Cc = 0.0f;
            #pragma unroll
            for (int w = 0; w < 8; ++w) { S += redS[w]; Cc += redC[w]; }
            int c = (int)(Cc + 0.5f);
            if (c == cprev_sh || c <= 0) done_sh = 1;
            else { cprev_sh = c; tau_sh = (S - 1.0f) / (float)c; }
        }
        __syncthreads();
        if (done_sh) break;
    }
    const float tau = tau_sh;

    int mycnt = 0;
    #pragma unroll
    for (int i = 0; i < 32; ++i)
        if (zr[i] > tau) mycnt++;

    int csum = mycnt;
    #pragma unroll
    for (int o = 1; o < 32; o <<= 1) {
        int n = __shfl_up_sync(0xffffffffu, csum, o);
        if (lane >= o) csum += n;
    }
    if (lane == 31) wtot[warp] = csum;
    __syncthreads();
    if (warp == 0 && lane < 8) {
        int t = wtot[lane];
        #pragma unroll
        for (int o = 1; o < 8; o <<= 1) {
            int n = __shfl_up_sync(0x000000ffu, t, o);
            if (lane >= o) t += n;
        }
        wpre[lane] = t;
    }
    __syncthreads();
    const int nnz = wpre[7];
    if (nnz <= SPX_CAP) {
        int off = (warp ? wpre[warp - 1] : 0) + csum - mycnt;
        #pragma unroll
        for (int l = 0; l < 4; ++l) {
            int base = 8 * (tid + l * 256);
            #pragma unroll
            for (int j = 0; j < 8; ++j)
                if (zr[l * 8 + j] > tau) idxs[off++] = (unsigned short)(base + j);
        }
    }
    __syncthreads();

    float4 acc = make_float4(0.f, 0.f, 0.f, 0.f);
    const float4* mem4 = (const float4*)mem;
    if (nnz <= SPX_CAP) {
        #pragma unroll 4
        for (int j = 0; j < nnz; ++j) {
            int m = idxs[j];
            float w = __half2float(zh[m]) - tau;
            float4 v = mem4[(size_t)m * 256 + tid];
            acc.x += w * v.x; acc.y += w * v.y;
            acc.z += w * v.z; acc.w += w * v.w;
        }
    } else {
        for (int m = 0; m < NM; ++m) {
            float w = __half2float(zh[m]) - tau;
            if (w > 0.0f) {
                float4 v = mem4[(size_t)m * 256 + tid];
                acc.x += w * v.x; acc.y += w * v.y;
                acc.z += w * v.z; acc.w += w * v.w;
            }
        }
    }
    half* ph = g_cat_h + (size_t)row * N2D + ND + tid * 4;
    ph[0] = __float2half_rn(acc.x); ph[1] = __float2half_rn(acc.y);
    ph[2] = __float2half_rn(acc.z); ph[3] = __float2half_rn(acc.w);
}

// ---------------------------------------------------------------
// launch
// ---------------------------------------------------------------
extern "C" void kernel_launch(void* const* d_in, const int* in_sizes, int n_in,
                              void* d_out, int out_size) {
    const float* enc  = (const float*)d_in[0];  // [4096,1024]
    const float* mem  = (const float*)d_in[1];  // [8192,1024]
    const float* fc1w = (const float*)d_in[2];  // [4096,2048]
    const float* fc1b = (const float*)d_in[3];  // [4096]
    const float* fc2w = (const float*)d_in[4];  // [1000,4096]
    const float* fc2b = (const float*)d_in[5];  // [1000]
    float* out = (float*)d_out;                 // [4096,1000]

    void *p_xinv, *p_yinv, *p_sim, *p_cath, *p_memh, *p_hidh, *p_w1h, *p_w2h;
    cudaGetSymbolAddress(&p_xinv, g_xinv);
    cudaGetSymbolAddress(&p_yinv, g_yinv);
    cudaGetSymbolAddress(&p_sim,  g_sim);
    cudaGetSymbolAddress(&p_cath, g_cat_h);
    cudaGetSymbolAddress(&p_memh, g_mem_h);
    cudaGetSymbolAddress(&p_hidh, g_hid_h);
    cudaGetSymbolAddress(&p_w1h,  g_w1_h);
    cudaGetSymbolAddress(&p_w2h,  g_w2_h);

    cudaFuncSetAttribute(tc_gemm<0>, cudaFuncAttributeMaxDynamicSharedMemorySize, GEMM_SMEM);
    cudaFuncSetAttribute(tc_gemm<1>, cudaFuncAttributeMaxDynamicSharedMemorySize, GEMM_SMEM);
    cudaFuncSetAttribute(tc_gemm<2>, cudaFuncAttributeMaxDynamicSharedMemorySize, GEMM_SMEM);

    // 1) norms + rounds
    norm_enc_kernel<<<NB, 256>>>(enc);
    norm_mem_kernel<<<NM, 256>>>(mem);
    round_kernel<<<(int)(((size_t)NH * N2D / 4) / 256), 256>>>(fc1w, (half*)p_w1h);
    round_pad_w2_kernel<<<NOUTP, 256>>>(fc2w);

    // 2) sim = (enc @ mem^T) * xinv[row] * yinv[col]  -> fp16
    tc_gemm<0><<<dim3(NM / 256, NB / 128), 256, GEMM_SMEM>>>(
        NM, ND, N2D, ND, NM,
        (const half*)p_cath, (const half*)p_memh,
        nullptr, (half*)p_sim,
        (const float*)p_xinv, (const float*)p_yinv, nullptr);

    // 3) sparsemax + sparse memory vector -> concat right half
    sparsemax_mv_kernel<<<NB, 256>>>(mem);

    // 4) hidden = relu(concat @ fc1w^T + b) -> fp16 store
    tc_gemm<1><<<dim3(NH / 256, NB / 128), 256, GEMM_SMEM>>>(
        NH, N2D, N2D, N2D, NH,
        (const half*)p_cath, (const half*)p_w1h,
        nullptr, (half*)p_hidh,
        nullptr, nullptr, fc1b);

    // 5) out = hidden @ fc2w^T + b  (padded N, store-guarded)
    tc_gemm<2><<<dim3(NOUTP / 256, NB / 128), 256, GEMM_SMEM>>>(
        NOUTP, NH, NH, NH, NOUT,
        (const half*)p_hidh, (const half*)p_w2h,
        out, nullptr,
        nullptr, nullptr, fc2b);
}

// round 14
// speedup vs baseline: 6.6723x; 1.0817x over previous
#include <cuda_runtime.h>
#include <cuda_fp16.h>
#include <cstdint>

// Problem constants
#define NB   4096   // batch B
#define NM   8192   // memory rows M
#define ND   1024   // dim D
#define NOUT 1000   // output classes
#define NOUTP 1024  // padded output cols
#define NH   4096   // 4*D hidden
#define N2D  2048   // 2*D concat width

// -------- scratch (device globals; no allocation allowed) --------
__device__ float g_xinv[NB];
__device__ float g_yinv[NM];
__device__ half  g_sim[(size_t)NB * NM];        // 64 MB (fp16 sims)
__device__ half  g_cat_h[(size_t)NB * N2D];     // 16 MB  [enc | mv] rounded
__device__ half  g_mem_h[(size_t)NM * ND];      // 16 MB
__device__ half  g_hid_h[(size_t)NB * NH];      // 32 MB
__device__ half  g_w1_h[(size_t)NH * N2D];      // 16 MB
__device__ half  g_w2_h[(size_t)NOUTP * NH];    // 8 MB (padded)

// ---------------------------------------------------------------
// helpers
// ---------------------------------------------------------------
__device__ __forceinline__ uint32_t cvta_smem(const void* p) {
    uint32_t a;
    asm("{ .reg .u64 t; cvta.to.shared.u64 t, %1; cvt.u32.u64 %0, t; }"
        : "=r"(a) : "l"(p));
    return a;
}

__device__ __forceinline__ void cp16(uint32_t dst, const void* src) {
    asm volatile("cp.async.cg.shared.global [%0], [%1], 16;" :: "r"(dst), "l"(src));
}

__device__ __forceinline__ void mma_fp16(float* d, const uint32_t* a, const uint32_t* b) {
    asm volatile(
        "mma.sync.aligned.m16n8k16.row.col.f32.f16.f16.f32 "
        "{%0,%1,%2,%3}, {%4,%5,%6,%7}, {%8,%9}, {%0,%1,%2,%3};"
        : "+f"(d[0]), "+f"(d[1]), "+f"(d[2]), "+f"(d[3])
        : "r"(a[0]), "r"(a[1]), "r"(a[2]), "r"(a[3]), "r"(b[0]), "r"(b[1]));
}

__device__ __forceinline__ void ldsm_x4(uint32_t* r, uint32_t addr) {
    asm volatile("ldmatrix.sync.aligned.m8n8.x4.shared.b16 {%0,%1,%2,%3}, [%4];"
                 : "=r"(r[0]), "=r"(r[1]), "=r"(r[2]), "=r"(r[3]) : "r"(addr));
}

// ---------------------------------------------------------------
// block reduce (256 threads)
// ---------------------------------------------------------------
__device__ __forceinline__ float blockReduceSum256(float v, float* red) {
    __syncthreads();
    #pragma unroll
    for (int o = 16; o > 0; o >>= 1) v += __shfl_down_sync(0xffffffffu, v, o);
    int warp = threadIdx.x >> 5, lane = threadIdx.x & 31;
    if (lane == 0) red[warp] = v;
    __syncthreads();
    if (warp == 0) {
        v = (lane < 8) ? red[lane] : 0.0f;
        #pragma unroll
        for (int o = 4; o > 0; o >>= 1) v += __shfl_down_sync(0xffffffffu, v, o);
        if (lane == 0) red[0] = v;
    }
    __syncthreads();
    return red[0];
}

// ---------------------------------------------------------------
// fused prologue: one launch covers
//   [0, 4096)        enc rows:  1/||x|| + fp16 round -> cat left
//   [4096, 12288)    mem rows:  1/||y|| + fp16 round
//   [12288, 20480)   fc1w round (1024 floats per block)
//   [20480, 21504)   fc2w round + zero-pad row
// ---------------------------------------------------------------
#define PREP_ENC_END 4096
#define PREP_MEM_END 12288
#define PREP_W1_END  20480
#define PREP_BLOCKS  21504

__global__ __launch_bounds__(256) void prep_kernel(
    const float* __restrict__ enc, const float* __restrict__ mem,
    const float* __restrict__ fc1w, const float* __restrict__ fc2w)
{
    __shared__ float red[8];
    const int bid = blockIdx.x, tid = threadIdx.x;

    if (bid < PREP_ENC_END) {
        const int row = bid;
        float4 v = ((const float4*)(enc + (size_t)row * ND))[tid];
        float s = v.x*v.x + v.y*v.y + v.z*v.z + v.w*v.w;
        s = blockReduceSum256(s, red);
        if (tid == 0) g_xinv[row] = rsqrtf(s + 1e-6f);
        half* ph = g_cat_h + (size_t)row * N2D + tid * 4;
        ph[0] = __float2half_rn(v.x); ph[1] = __float2half_rn(v.y);
        ph[2] = __float2half_rn(v.z); ph[3] = __float2half_rn(v.w);
    } else if (bid < PREP_MEM_END) {
        const int row = bid - PREP_ENC_END;
        float4 v = ((const float4*)(mem + (size_t)row * ND))[tid];
        float s = v.x*v.x + v.y*v.y + v.z*v.z + v.w*v.w;
        s = blockReduceSum256(s, red);
        if (tid == 0) g_yinv[row] = rsqrtf(s + 1e-6f);
        half* ph = g_mem_h + (size_t)row * ND + tid * 4;
        ph[0] = __float2half_rn(v.x); ph[1] = __float2half_rn(v.y);
        ph[2] = __float2half_rn(v.z); ph[3] = __float2half_rn(v.w);
    } else if (bid < PREP_W1_END) {
        const size_t i = (size_t)(bid - PREP_MEM_END) * 256 + tid;
        float4 v = ((const float4*)fc1w)[i];
        half* p = g_w1_h + i * 4;
        p[0] = __float2half_rn(v.x); p[1] = __float2half_rn(v.y);
        p[2] = __float2half_rn(v.z); p[3] = __float2half_rn(v.w);
    } else {
        const int row = bid - PREP_W1_END;   // 0..1023
        #pragma unroll
        for (int lq = 0; lq < 4; ++lq) {
            int idx = tid + 256 * lq;
            float4 v = make_float4(0.f, 0.f, 0.f, 0.f);
            if (row < NOUT) v = ((const float4*)(fc2w + (size_t)row * NH))[idx];
            half* p = g_w2_h + (size_t)row * NH + idx * 4;
            p[0] = __float2half_rn(v.x); p[1] = __float2half_rn(v.y);
            p[2] = __float2half_rn(v.z); p[3] = __float2half_rn(v.w);
        }
    }
}

// ---------------------------------------------------------------
// single-pass fp16 GEMM (mma.sync.m16n8k16 + ldmatrix):
//   C[M,N] = A[M,K] @ B[N,K]^T, fp32 accum
// 128x128 CTA tile, BK=64, 3-stage cp.async pipeline, 2 CTAs/SM,
// 256 threads (8 warps 2x4, 64x32 warp tiles).
// Coalesced tile loads (8 lanes per 128B row).
// EPI 0/1: smem-staged coalesced fp16 stores; EPI 2: guarded fp32.
// ---------------------------------------------------------------
#define BKE     64
#define ROW_B   144                      // 128 + 16 pad
#define A_T     (128 * ROW_B)            // 18432
#define B_T     (128 * ROW_B)            // 18432
#define STAGE_B (A_T + B_T)              // 36864
#define NSTAGE  3
#define GEMM_SMEM (NSTAGE * STAGE_B)     // 110592
#define OUT_SROW 136                     // staging stride in halves (272 B)

template<int EPI>
__global__ __launch_bounds__(256, 2) void tc_gemm(
    int N, int K, int lda, int ldb, int Nout,
    const half* __restrict__ A0, const half* __restrict__ B0,
    float* __restrict__ C, half* __restrict__ Ch,
    const float* __restrict__ xinv, const float* __restrict__ yinv,
    const float* __restrict__ bias)
{
    extern __shared__ __align__(1024) char smraw[];
    const uint32_t smemU = cvta_smem(smraw);

    const int tid  = threadIdx.x;
    const int lane = tid & 31;
    const int wid  = tid >> 5;
    const int wm   = wid & 1;          // 0..1 (64-row block)
    const int wn   = wid >> 1;         // 0..3 (32-col block)
    const int row0 = blockIdx.y * 128;
    const int col0 = blockIdx.x * 128;

    const int nkc = K / BKE;

    // Coalesced global->smem: 8 lanes per row (16B each)
    const int wr  = tid >> 3;          // 0..31 base row
    const int lc8 = tid & 7;
    const uint32_t aBase = smemU + wr * ROW_B + lc8 * 16;
    const uint32_t bBase = smemU + A_T + wr * ROW_B + lc8 * 16;

    auto do_load = [&](int ck, int s) {
        const uint32_t so = s * STAGE_B;
        const half* ga = A0 + (size_t)(row0 + wr) * lda + ck * BKE + lc8 * 8;
        const half* gb = B0 + (size_t)(col0 + wr) * ldb + ck * BKE + lc8 * 8;
        #pragma unroll
        for (int i = 0; i < 4; ++i) {
            cp16(aBase + so + i * (32 * ROW_B), ga + (size_t)(32 * i) * lda);
            cp16(bBase + so + i * (32 * ROW_B), gb + (size_t)(32 * i) * ldb);
        }
    };

    float acc[4][4][4];
    #pragma unroll
    for (int mt = 0; mt < 4; ++mt)
        #pragma unroll
        for (int nt = 0; nt < 4; ++nt)
            #pragma unroll
            for (int c = 0; c < 4; ++c) acc[mt][nt][c] = 0.0f;

    do_load(0, 0);
    asm volatile("cp.async.commit_group;" ::: "memory");
    do_load(1, 1);
    asm volatile("cp.async.commit_group;" ::: "memory");

    // ldmatrix lane bases
    const uint32_t aFragBase = smemU + (wm * 64 + (lane & 15)) * ROW_B + (lane >> 4) * 16;
    const uint32_t bFragBase = smemU + A_T +
        (wn * 32 + (lane & 7) + ((lane >> 4) & 1) * 8) * ROW_B + ((lane >> 3) & 1) * 16;

    for (int it = 0; it < nkc; ++it) {
        if (it + 2 < nkc) {
            asm volatile("cp.async.wait_group 1;" ::: "memory");
        } else {
            asm volatile("cp.async.wait_group 0;" ::: "memory");
        }
        __syncthreads();
        if (it + 2 < nkc) {
            do_load(it + 2, (it + 2) % NSTAGE);
            asm volatile("cp.async.commit_group;" ::: "memory");
        }

        const uint32_t so = (it % NSTAGE) * STAGE_B;

        #pragma unroll
        for (int ks = 0; ks < 4; ++ks) {
            const uint32_t ko = ks * 32;
            uint32_t bfr[8];   // 4 n-tiles x 2 regs
            #pragma unroll
            for (int p = 0; p < 2; ++p)
                ldsm_x4(&bfr[4 * p], bFragBase + so + p * (16 * ROW_B) + ko);

            uint32_t afr[4][4];
            #pragma unroll
            for (int mt = 0; mt < 4; ++mt)
                ldsm_x4(afr[mt], aFragBase + so + mt * (16 * ROW_B) + ko);
            #pragma unroll
            for (int mt = 0; mt < 4; ++mt)
                #pragma unroll
                for (int nt = 0; nt < 4; ++nt)
                    mma_fp16(acc[mt][nt], afr[mt], &bfr[nt * 2]);
        }
    }

    // epilogue
    const int r = lane >> 2;
    const int q = lane & 3;

    if (EPI == 2) {
        #pragma unroll
        for (int mt = 0; mt < 4; ++mt) {
            const int gr0 = row0 + wm * 64 + mt * 16 + r;
            #pragma unroll
            for (int half_ = 0; half_ < 2; ++half_) {
                const int gr = gr0 + half_ * 8;
                #pragma unroll
                for (int nt = 0; nt < 4; ++nt) {
                    const int gc = col0 + wn * 32 + nt * 8 + q * 2;
                    if (gc < Nout) {
                        float2 o = make_float2(acc[mt][nt][half_ * 2 + 0] + bias[gc],
                                               acc[mt][nt][half_ * 2 + 1] + bias[gc + 1]);
                        *(float2*)(C + (size_t)gr * Nout + gc) = o;
                    }
                }
            }
        }
    } else {
        __syncthreads();
        half* stg = (half*)smraw;
        #pragma unroll
        for (int mt = 0; mt < 4; ++mt) {
            const int lr0 = wm * 64 + mt * 16 + r;
            #pragma unroll
            for (int half_ = 0; half_ < 2; ++half_) {
                const int lr = lr0 + half_ * 8;
                float xr = 0.0f;
                if (EPI == 0) xr = xinv[row0 + lr];
                #pragma unroll
                for (int nt = 0; nt < 4; ++nt) {
                    const int lcL = wn * 32 + nt * 8 + q * 2;
                    float v0 = acc[mt][nt][half_ * 2 + 0];
                    float v1 = acc[mt][nt][half_ * 2 + 1];
                    __half2 hh;
                    const int gc = col0 + lcL;
                    if (EPI == 0) {
                        hh.x = __float2half_rn(v0 * xr * yinv[gc]);
                        hh.y = __float2half_rn(v1 * xr * yinv[gc + 1]);
                    } else {
                        hh.x = __float2half_rn(fmaxf(v0 + bias[gc], 0.0f));
                        hh.y = __float2half_rn(fmaxf(v1 + bias[gc + 1], 0.0f));
                    }
                    *(__half2*)(stg + lr * OUT_SROW + lcL) = hh;
                }
            }
        }
        __syncthreads();
        // coalesced: 128 rows x 16 uint4 (256B/row)
        #pragma unroll
        for (int i = 0; i < 8; ++i) {
            const int idx  = tid + i * 256;
            const int rrow = idx >> 4;
            const int slot = idx & 15;
            uint4 v = *(const uint4*)(stg + rrow * OUT_SROW + slot * 8);
            *(uint4*)(Ch + (size_t)(row0 + rrow) * N + col0 + slot * 8) = v;
        }
    }
}

// ---------------------------------------------------------------
// Fused sparsemax (Michelot, sort-free, register-resident) + sparse
// memory-vector gather.  z input is fp16 (g_sim); math in fp32 regs.
// ---------------------------------------------------------------
#define SPX_CAP 4096
__global__ __launch_bounds__(256) void sparsemax_mv_kernel(const float* __restrict__ mem) {
    __shared__ __align__(16) half zh[NM];    // 16 KB
    __shared__ unsigned short idxs[SPX_CAP]; // 8 KB
    __shared__ float redS[8];
    __shared__ float redC[8];
    __shared__ int   wtot[8];
    __shared__ int   wpre[8];
    __shared__ float tau_sh;
    __shared__ int   cprev_sh;
    __shared__ int   done_sh;

    const int row = blockIdx.x;
    const int tid = threadIdx.x;
    const int warp = tid >> 5, lane = tid & 31;

    float zr[32];
    {
        const uint4* src = (const uint4*)(g_sim + (size_t)row * NM);
        #pragma unroll
        for (int l = 0; l < 4; ++l) {
            uint4 raw = src[tid + l * 256];
            ((uint4*)zh)[tid + l * 256] = raw;
            const __half2* hp = (const __half2*)&raw;
            #pragma unroll
            for (int k = 0; k < 4; ++k) {
                float2 f = __half22float2(hp[k]);
                zr[l * 8 + 2 * k]     = f.x;
                zr[l * 8 + 2 * k + 1] = f.y;
            }
        }
    }
    __syncthreads();

    {
        float s = 0.0f;
        #pragma unroll
        for (int i = 0; i < 32; ++i) s += zr[i];
        s = blockReduceSum256(s, redS);
        if (tid == 0) {
            tau_sh = (s - 1.0f) / (float)NM;
            cprev_sh = NM;
            done_sh = 0;
        }
        __syncthreads();
    }

    for (int it = 0; it < 64; ++it) {
        float tau = tau_sh;
        float ls = 0.0f, lc = 0.0f;
        #pragma unroll
        for (int i = 0; i < 32; ++i)
            if (zr[i] > tau) { ls += zr[i]; lc += 1.0f; }
        #pragma unroll
        for (int o = 16; o > 0; o >>= 1) {
            ls += __shfl_down_sync(0xffffffffu, ls, o);
            lc += __shfl_down_sync(0xffffffffu, lc, o);
        }
        if (lane == 0) { redS[warp] = ls; redC[warp] = lc; }
        __syncthreads();
        if (tid == 0) {
            float S = 0.0f, Cc = 0.0f;
            #pragma unroll
            for (int w = 0; w < 8; ++w) { S += redS[w]; Cc += redC[w]; }
            int c = (int)(Cc + 0.5f);
            if (c == cprev_sh || c <= 0) done_sh = 1;
            else { cprev_sh = c; tau_sh = (S - 1.0f) / (float)c; }
        }
        __syncthreads();
        if (done_sh) break;
    }
    const float tau = tau_sh;

    int mycnt = 0;
    #pragma unroll
    for (int i = 0; i < 32; ++i)
        if (zr[i] > tau) mycnt++;

    int csum = mycnt;
    #pragma unroll
    for (int o = 1; o < 32; o <<= 1) {
        int n = __shfl_up_sync(0xffffffffu, csum, o);
        if (lane >= o) csum += n;
    }
    if (lane == 31) wtot[warp] = csum;
    __syncthreads();
    if (warp == 0 && lane < 8) {
        int t = wtot[lane];
        #pragma unroll
        for (int o = 1; o < 8; o <<= 1) {
            int n = __shfl_up_sync(0x000000ffu, t, o);
            if (lane >= o) t += n;
        }
        wpre[lane] = t;
    }
    __syncthreads();
    const int nnz = wpre[7];
    if (nnz <= SPX_CAP) {
        int off = (warp ? wpre[warp - 1] : 0) + csum - mycnt;
        #pragma unroll
        for (int l = 0; l < 4; ++l) {
            int base = 8 * (tid + l * 256);
            #pragma unroll
            for (int j = 0; j < 8; ++j)
                if (zr[l * 8 + j] > tau) idxs[off++] = (unsigned short)(base + j);
        }
    }
    __syncthreads();

    float4 acc = make_float4(0.f, 0.f, 0.f, 0.f);
    const float4* mem4 = (const float4*)mem;
    if (nnz <= SPX_CAP) {
        #pragma unroll 4
        for (int j = 0; j < nnz; ++j) {
            int m = idxs[j];
            float w = __half2float(zh[m]) - tau;
            float4 v = mem4[(size_t)m * 256 + tid];
            acc.x += w * v.x; acc.y += w * v.y;
            acc.z += w * v.z; acc.w += w * v.w;
        }
    } else {
        for (int m = 0; m < NM; ++m) {
            float w = __half2float(zh[m]) - tau;
            if (w > 0.0f) {
                float4 v = mem4[(size_t)m * 256 + tid];
                acc.x += w * v.x; acc.y += w * v.y;
                acc.z += w * v.z; acc.w += w * v.w;
            }
        }
    }
    half* ph = g_cat_h + (size_t)row * N2D + ND + tid * 4;
    ph[0] = __float2half_rn(acc.x); ph[1] = __float2half_rn(acc.y);
    ph[2] = __float2half_rn(acc.z); ph[3] = __float2half_rn(acc.w);
}

// ---------------------------------------------------------------
// launch
// ---------------------------------------------------------------
extern "C" void kernel_launch(void* const* d_in, const int* in_sizes, int n_in,
                              void* d_out, int out_size) {
    const float* enc  = (const float*)d_in[0];  // [4096,1024]
    const float* mem  = (const float*)d_in[1];  // [8192,1024]
    const float* fc1w = (const float*)d_in[2];  // [4096,2048]
    const float* fc1b = (const float*)d_in[3];  // [4096]
    const float* fc2w = (const float*)d_in[4];  // [1000,4096]
    const float* fc2b = (const float*)d_in[5];  // [1000]
    float* out = (float*)d_out;                 // [4096,1000]

    void *p_xinv, *p_yinv, *p_sim, *p_cath, *p_memh, *p_hidh, *p_w1h, *p_w2h;
    cudaGetSymbolAddress(&p_xinv, g_xinv);
    cudaGetSymbolAddress(&p_yinv, g_yinv);
    cudaGetSymbolAddress(&p_sim,  g_sim);
    cudaGetSymbolAddress(&p_cath, g_cat_h);
    cudaGetSymbolAddress(&p_memh, g_mem_h);
    cudaGetSymbolAddress(&p_hidh, g_hid_h);
    cudaGetSymbolAddress(&p_w1h,  g_w1_h);
    cudaGetSymbolAddress(&p_w2h,  g_w2_h);

    cudaFuncSetAttribute(tc_gemm<0>, cudaFuncAttributeMaxDynamicSharedMemorySize, GEMM_SMEM);
    cudaFuncSetAttribute(tc_gemm<1>, cudaFuncAttributeMaxDynamicSharedMemorySize, GEMM_SMEM);
    cudaFuncSetAttribute(tc_gemm<2>, cudaFuncAttributeMaxDynamicSharedMemorySize, GEMM_SMEM);

    // 1) fused prologue (norms + rounds) in ONE launch
    prep_kernel<<<PREP_BLOCKS, 256>>>(enc, mem, fc1w, fc2w);

    // 2) sim = (enc @ mem^T) * xinv[row] * yinv[col]  -> fp16
    tc_gemm<0><<<dim3(NM / 128, NB / 128), 256, GEMM_SMEM>>>(
        NM, ND, N2D, ND, NM,
        (const half*)p_cath, (const half*)p_memh,
        nullptr, (half*)p_sim,
        (const float*)p_xinv, (const float*)p_yinv, nullptr);

    // 3) sparsemax + sparse memory vector -> concat right half
    sparsemax_mv_kernel<<<NB, 256>>>(mem);

    // 4) hidden = relu(concat @ fc1w^T + b) -> fp16 store
    tc_gemm<1><<<dim3(NH / 128, NB / 128), 256, GEMM_SMEM>>>(
        NH, N2D, N2D, N2D, NH,
        (const half*)p_cath, (const half*)p_w1h,
        nullptr, (half*)p_hidh,
        nullptr, nullptr, fc1b);

    // 5) out = hidden @ fc2w^T + b  (padded N, store-guarded)
    tc_gemm<2><<<dim3(NOUTP / 128, NB / 128), 256, GEMM_SMEM>>>(
        NOUTP, NH, NH, NH, NOUT,
        (const half*)p_hidh, (const half*)p_w2h,
        out, nullptr,
        nullptr, nullptr, fc2b);
}